// round 11
// baseline (speedup 1.0000x reference)
#include <cuda_runtime.h>
#include <cuda_bf16.h>
#include <math.h>

// Problem constants
#define NN     50000
#define FIN    256
#define NH     4
#define NR     4
#define FF     64
#define NE     500000
#define CPROJ  1024          // NH*NR*FF
#define CTOT   1280          // CPROJ + NH*FF (skip)
#define NSEG   (NN * NR)     // 200000 (trg, rel) segments
#define NB1    ((NSEG + 1023) / 1024)   // 196 scan blocks

// ---------------- scratch (device globals; no allocation allowed) ----------------
// proj layout PERMUTED: col = r*256 + h*64 + f   (skip still at cols 1024..1279, h*64+f)
__device__ float         g_ps[(size_t)NN * CTOT];
__device__ unsigned      g_aggp[(size_t)NSEG * NH * FF];   // packed bf16 (hi lo) per value
__device__ float         g_ssrc[(size_t)NN * NH * NR];     // [n*16 + r*4 + h]
__device__ float         g_strg[(size_t)NN * NH * NR];
__device__ unsigned      g_m_u[NR * NH];                   // index q = r*4 + h
__device__ __nv_bfloat16 g_bext[(size_t)CTOT * 512];       // [c'][512] = [W_hi | W_lo]
// edge sort scratch
__device__ int           g_cnt[NSEG];
__device__ int           g_off[NSEG + 1];
__device__ int           g_cur[NSEG];
__device__ int           g_bsum[256];
__device__ int           g_psrc[NE];                       // src[], permuted by segment

// ---------------- helpers ----------------
__device__ __forceinline__ unsigned fenc(float f) {
    unsigned u = __float_as_uint(f);
    return (u & 0x80000000u) ? ~u : (u | 0x80000000u);
}
__device__ __forceinline__ float fdec(unsigned u) {
    return (u & 0x80000000u) ? __uint_as_float(u & 0x7fffffffu) : __uint_as_float(~u);
}
__device__ __forceinline__ void bsplit(float w, __nv_bfloat16& hi, __nv_bfloat16& lo) {
    hi = __float2bfloat16(w);
    lo = __float2bfloat16(w - __bfloat162float(hi));
}
__device__ __forceinline__ unsigned bpack(__nv_bfloat16 h, __nv_bfloat16 l) {
    return ((unsigned)__bfloat16_as_ushort(l) << 16) | (unsigned)__bfloat16_as_ushort(h);
}
__device__ __forceinline__ void mma_bf16(float* c, unsigned a0, unsigned a1, unsigned a2,
                                         unsigned a3, unsigned b0, unsigned b1) {
    asm volatile(
        "mma.sync.aligned.m16n8k16.row.col.f32.bf16.bf16.f32 "
        "{%0,%1,%2,%3}, {%4,%5,%6,%7}, {%8,%9}, {%0,%1,%2,%3};\n"
        : "+f"(c[0]), "+f"(c[1]), "+f"(c[2]), "+f"(c[3])
        : "r"(a0), "r"(a1), "r"(a2), "r"(a3), "r"(b0), "r"(b1));
}
__device__ __forceinline__ void ldsm4(unsigned& r0, unsigned& r1, unsigned& r2, unsigned& r3,
                                      const void* p) {
    unsigned addr = (unsigned)__cvta_generic_to_shared(p);
    asm volatile("ldmatrix.sync.aligned.m8n8.x4.shared.b16 {%0,%1,%2,%3}, [%4];\n"
                 : "=r"(r0), "=r"(r1), "=r"(r2), "=r"(r3) : "r"(addr));
}
// split 8 fp32 into 8 hi-bf16 and 8 lo-bf16 (memory order preserved)
__device__ __forceinline__ void split8(const float4& a, const float4& b, uint4& hv, uint4& lv) {
    __nv_bfloat16 h0, l0, h1, l1;
    bsplit(a.x, h0, l0); bsplit(a.y, h1, l1); hv.x = bpack(h0, h1); lv.x = bpack(l0, l1);
    bsplit(a.z, h0, l0); bsplit(a.w, h1, l1); hv.y = bpack(h0, h1); lv.y = bpack(l0, l1);
    bsplit(b.x, h0, l0); bsplit(b.y, h1, l1); hv.z = bpack(h0, h1); lv.z = bpack(l0, l1);
    bsplit(b.z, h0, l0); bsplit(b.w, h1, l1); hv.w = bpack(h0, h1); lv.w = bpack(l0, l1);
}

// ---------------- prep: split weights with PERMUTED proj columns ----------------
__global__ void prep_wext_kernel(const float* __restrict__ Wp, const float* __restrict__ Ws) {
    int idx = blockIdx.x * blockDim.x + threadIdx.x;
    if (idx >= CTOT * FIN) return;
    int c = idx >> 8, k = idx & 255;
    float w; int c2;
    if (c < CPROJ) {
        w = Wp[idx];
        int h = c >> 8, r = (c >> 6) & 3, f = c & 63;
        c2 = r * 256 + h * 64 + f;          // permuted: [r][h][f]
    } else {
        w = Ws[(c - CPROJ) * FIN + k];
        c2 = c;
    }
    __nv_bfloat16 hi, lo; bsplit(w, hi, lo);
    size_t b = (size_t)c2 * 512;
    g_bext[b + k] = hi; g_bext[b + 256 + k] = lo;
}

// ---------------- zero small scratch ----------------
__global__ void zero_kernel() {
    int idx = blockIdx.x * blockDim.x + threadIdx.x;
    for (int i = idx; i < NSEG; i += gridDim.x * blockDim.x) g_cnt[i] = 0;
    if (idx < NR * NH) g_m_u[idx] = 0u;
}

// ---------------- K2: bf16 TC GEMM — reg-prefetch, in-kernel x split, fused scores -------
// C[N,1280] = x[N,256] @ Wcat^T via split-bf16: hi*hi + hi*lo + lo*hi
#define GSTR 40   // smem row stride in halves (80B) — conflict-free ldmatrix
__global__ void __launch_bounds__(256) gemm_bf16_kernel(const float* __restrict__ X,
                                                        const float* __restrict__ sv_src,
                                                        const float* __restrict__ sv_trg) {
    __shared__ __nv_bfloat16 Ah[128 * GSTR];
    __shared__ __nv_bfloat16 Al[128 * GSTR];
    __shared__ __nv_bfloat16 Bh[128 * GSTR];
    __shared__ __nv_bfloat16 Bl[128 * GSTR];
    __shared__ float sred[512];

    int t = threadIdx.x;
    int lane = t & 31, w = t >> 5;
    int wm = w >> 2, wn = w & 3;           // wm 0..1 (64 rows), wn 0..3 (32 cols)
    int g = lane >> 2, tg = lane & 3;
    int row0 = blockIdx.y * 128;
    int col0 = blockIdx.x * 128;

    float acc[4][4][4];
#pragma unroll
    for (int i = 0; i < 4; i++)
#pragma unroll
        for (int j = 0; j < 4; j++)
#pragma unroll
            for (int q = 0; q < 4; q++) acc[i][j][q] = 0.f;

    int r0v = t >> 2;                 // 0..63
    int kcv = (t & 3) * 8;            // 0,8,16,24 (float/half offset within 32-wide chunk)

    int fr = lane & 15;
    int fcb = (lane >> 4) * 8;

    int ga0 = row0 + r0v, ga1 = row0 + r0v + 64;
    bool p0 = ga0 < NN, p1 = ga1 < NN;
    const float* xp0 = X + (size_t)(p0 ? ga0 : 0) * FIN + kcv;
    const float* xp1 = X + (size_t)(p1 ? ga1 : 0) * FIN + kcv;
    const __nv_bfloat16* bp0 = g_bext + (size_t)(col0 + r0v) * 512 + kcv;
    const __nv_bfloat16* bp1 = g_bext + (size_t)(col0 + r0v + 64) * 512 + kcv;
    float4 zf = make_float4(0.f, 0.f, 0.f, 0.f);

    float4 xa0, xa1, xa2, xa3, bv0, bv1, bv2, bv3;
    // prefetch chunk 0
    {
        xa0 = p0 ? *reinterpret_cast<const float4*>(xp0)     : zf;
        xa1 = p0 ? *reinterpret_cast<const float4*>(xp0 + 4) : zf;
        xa2 = p1 ? *reinterpret_cast<const float4*>(xp1)     : zf;
        xa3 = p1 ? *reinterpret_cast<const float4*>(xp1 + 4) : zf;
        bv0 = *reinterpret_cast<const float4*>(bp0);
        bv1 = *reinterpret_cast<const float4*>(bp0 + 256);
        bv2 = *reinterpret_cast<const float4*>(bp1);
        bv3 = *reinterpret_cast<const float4*>(bp1 + 256);
    }

    for (int c = 0; c < 8; c++) {
        __syncthreads();
        // store prefetched chunk into smem (A split to hi/lo on the fly)
        uint4 hv, lv;
        split8(xa0, xa1, hv, lv);
        *reinterpret_cast<uint4*>(Ah + r0v * GSTR + kcv) = hv;
        *reinterpret_cast<uint4*>(Al + r0v * GSTR + kcv) = lv;
        split8(xa2, xa3, hv, lv);
        *reinterpret_cast<uint4*>(Ah + (r0v + 64) * GSTR + kcv) = hv;
        *reinterpret_cast<uint4*>(Al + (r0v + 64) * GSTR + kcv) = lv;
        *reinterpret_cast<float4*>(Bh + r0v * GSTR + kcv)        = bv0;
        *reinterpret_cast<float4*>(Bl + r0v * GSTR + kcv)        = bv1;
        *reinterpret_cast<float4*>(Bh + (r0v + 64) * GSTR + kcv) = bv2;
        *reinterpret_cast<float4*>(Bl + (r0v + 64) * GSTR + kcv) = bv3;
        __syncthreads();

        // prefetch chunk c+1 (hidden under the mma compute below)
        if (c < 7) {
            int k0 = (c + 1) * 32;
            xa0 = p0 ? *reinterpret_cast<const float4*>(xp0 + k0)     : zf;
            xa1 = p0 ? *reinterpret_cast<const float4*>(xp0 + k0 + 4) : zf;
            xa2 = p1 ? *reinterpret_cast<const float4*>(xp1 + k0)     : zf;
            xa3 = p1 ? *reinterpret_cast<const float4*>(xp1 + k0 + 4) : zf;
            bv0 = *reinterpret_cast<const float4*>(bp0 + k0);
            bv1 = *reinterpret_cast<const float4*>(bp0 + k0 + 256);
            bv2 = *reinterpret_cast<const float4*>(bp1 + k0);
            bv3 = *reinterpret_cast<const float4*>(bp1 + k0 + 256);
        }

#pragma unroll
        for (int kk = 0; kk < 32; kk += 16) {
            int fc = kk + fcb;
            unsigned bhf[2][4], blf[2][4];
#pragma unroll
            for (int np = 0; np < 2; np++) {
                int n = wn * 32 + np * 16 + fr;
                ldsm4(bhf[np][0], bhf[np][1], bhf[np][2], bhf[np][3], Bh + n * GSTR + fc);
                ldsm4(blf[np][0], blf[np][1], blf[np][2], blf[np][3], Bl + n * GSTR + fc);
            }
            // A_hi against B_hi and B_lo
#pragma unroll
            for (int mt = 0; mt < 4; mt++) {
                int r = wm * 64 + mt * 16 + fr;
                unsigned a0, a1, a2, a3;
                ldsm4(a0, a1, a2, a3, Ah + r * GSTR + fc);
#pragma unroll
                for (int nt = 0; nt < 4; nt++) {
                    int np = nt >> 1, sel = nt & 1;
                    mma_bf16(acc[mt][nt], a0, a1, a2, a3, bhf[np][sel], bhf[np][sel + 2]);
                    mma_bf16(acc[mt][nt], a0, a1, a2, a3, blf[np][sel], blf[np][sel + 2]);
                }
            }
            // A_lo against B_hi
#pragma unroll
            for (int mt = 0; mt < 4; mt++) {
                int r = wm * 64 + mt * 16 + fr;
                unsigned a0, a1, a2, a3;
                ldsm4(a0, a1, a2, a3, Al + r * GSTR + fc);
#pragma unroll
                for (int nt = 0; nt < 4; nt++) {
                    int np = nt >> 1, sel = nt & 1;
                    mma_bf16(acc[mt][nt], a0, a1, a2, a3, bhf[np][sel], bhf[np][sel + 2]);
                }
            }
        }
    }

    // write proj/skip
#pragma unroll
    for (int mt = 0; mt < 4; mt++)
#pragma unroll
        for (int nt = 0; nt < 4; nt++) {
            int row = row0 + wm * 64 + mt * 16 + g;
            int col = col0 + wn * 32 + nt * 8 + tg * 2;
            if (row < NN) {
                float2 o = make_float2(acc[mt][nt][0], acc[mt][nt][1]);
                *reinterpret_cast<float2*>(g_ps + (size_t)row * CTOT + col) = o;
            }
            if (row + 8 < NN) {
                float2 o = make_float2(acc[mt][nt][2], acc[mt][nt][3]);
                *reinterpret_cast<float2*>(g_ps + (size_t)(row + 8) * CTOT + col) = o;
            }
        }

    // fused attention-score epilogue (proj columns only; permuted slice q = r*4+h)
    if (col0 < CPROJ) {
        __syncthreads();
        for (int i = t; i < 512; i += 256) sred[i] = 0.f;
        __syncthreads();

        // score_src/score_trg are laid out [h][r][f]; our column c2 = (r*4+h)*64+f.
        // Un-permute: q = c2>>6, r = q>>2, h = q&3, orig = (h*4+r)*64 + (c2&63).
        float sv[4][2], tv[4][2];
#pragma unroll
        for (int nt = 0; nt < 4; nt++)
#pragma unroll
            for (int qc = 0; qc < 2; qc++) {
                int c2 = col0 + wn * 32 + nt * 8 + tg * 2 + qc;
                int q = c2 >> 6;
                int rr_ = q >> 2, hh_ = q & 3;
                int corig = (hh_ * 4 + rr_) * 64 + (c2 & 63);
                sv[nt][qc] = sv_src[corig];
                tv[nt][qc] = sv_trg[corig];
            }
        int p_idx = wn >> 1;
#pragma unroll
        for (int mt = 0; mt < 4; mt++) {
            float s0 = 0.f, s1 = 0.f, t0 = 0.f, t1 = 0.f;
#pragma unroll
            for (int nt = 0; nt < 4; nt++)
#pragma unroll
                for (int qc = 0; qc < 2; qc++) {
                    s0 = fmaf(acc[mt][nt][qc],     sv[nt][qc], s0);
                    t0 = fmaf(acc[mt][nt][qc],     tv[nt][qc], t0);
                    s1 = fmaf(acc[mt][nt][2 + qc], sv[nt][qc], s1);
                    t1 = fmaf(acc[mt][nt][2 + qc], tv[nt][qc], t1);
                }
#pragma unroll
            for (int off = 1; off < 4; off <<= 1) {
                s0 += __shfl_xor_sync(0xffffffffu, s0, off);
                t0 += __shfl_xor_sync(0xffffffffu, t0, off);
                s1 += __shfl_xor_sync(0xffffffffu, s1, off);
                t1 += __shfl_xor_sync(0xffffffffu, t1, off);
            }
            if (tg == 0) {
                int r0 = wm * 64 + mt * 16 + g;
                atomicAdd(&sred[r0 * 4 + p_idx],           s0);
                atomicAdd(&sred[r0 * 4 + 2 + p_idx],       t0);
                atomicAdd(&sred[(r0 + 8) * 4 + p_idx],     s1);
                atomicAdd(&sred[(r0 + 8) * 4 + 2 + p_idx], t1);
            }
        }
        __syncthreads();
        int p0s = col0 >> 6;   // permuted slice base (q index)
        for (int i = t; i < 512; i += 256) {
            int row = i >> 2, j = i & 3;
            int n = row0 + row;
            if (n < NN) {
                float vval = sred[i];
                int p = p0s + (j & 1);
                if (j < 2) g_ssrc[n * 16 + p] = vval;
                else       g_strg[n * 16 + p] = vval;
            }
        }
    }
}

// ---------------- edge pass 1: per-(rel,head) max (q = r*4+h) ----------------
__global__ void __launch_bounds__(256) edge1_kernel(const int* __restrict__ src,
                                                    const int* __restrict__ trg,
                                                    const int* __restrict__ rel) {
    __shared__ unsigned sm[16];
    int t = threadIdx.x;
    if (t < 16) sm[t] = 0u;
    __syncthreads();
    int e = blockIdx.x * 256 + t;
    if (e < NE) {
        int r = rel[e];
        float4 a = *reinterpret_cast<const float4*>(g_ssrc + (size_t)src[e] * 16 + r * 4);
        float4 b = *reinterpret_cast<const float4*>(g_strg + (size_t)trg[e] * 16 + r * 4);
        float vv[4] = {a.x + b.x, a.y + b.y, a.z + b.z, a.w + b.w};
#pragma unroll
        for (int h = 0; h < 4; h++) {
            float v = (vv[h] > 0.f) ? vv[h] : 0.2f * vv[h];
            atomicMax(&sm[r * 4 + h], fenc(v));
        }
    }
    __syncthreads();
    if (t < 16 && sm[t] != 0u) atomicMax(&g_m_u[t], sm[t]);
}

// ---------------- counting sort: hist / scan x3 / scatter ----------------
__global__ void hist_kernel(const int* __restrict__ trg, const int* __restrict__ rel) {
    int e = blockIdx.x * 256 + threadIdx.x;
    if (e < NE) atomicAdd(&g_cnt[trg[e] * 4 + rel[e]], 1);
}

__global__ void __launch_bounds__(1024) scan1_kernel() {
    __shared__ int sd[1024];
    int t = threadIdx.x;
    int i = blockIdx.x * 1024 + t;
    int v = (i < NSEG) ? g_cnt[i] : 0;
    sd[t] = v;
    __syncthreads();
#pragma unroll
    for (int off = 1; off < 1024; off <<= 1) {
        int u = (t >= off) ? sd[t - off] : 0;
        __syncthreads();
        sd[t] += u;
        __syncthreads();
    }
    if (i < NSEG) g_off[i] = sd[t] - v;
    if (t == 1023) g_bsum[blockIdx.x] = sd[t];
}

__global__ void __launch_bounds__(256) scan2_kernel() {
    __shared__ int sd[256];
    int t = threadIdx.x;
    int v = (t < NB1) ? g_bsum[t] : 0;
    sd[t] = v;
    __syncthreads();
#pragma unroll
    for (int off = 1; off < 256; off <<= 1) {
        int u = (t >= off) ? sd[t - off] : 0;
        __syncthreads();
        sd[t] += u;
        __syncthreads();
    }
    if (t < NB1) g_bsum[t] = sd[t] - v;
    if (t == 0) g_off[NSEG] = NE;
}

__global__ void __launch_bounds__(1024) scan3_kernel() {
    int i = blockIdx.x * 1024 + threadIdx.x;
    if (i < NSEG) {
        int o = g_off[i] + g_bsum[blockIdx.x];
        g_off[i] = o;
        g_cur[i] = o;
    }
}

__global__ void scatter_kernel(const int* __restrict__ src, const int* __restrict__ trg,
                               const int* __restrict__ rel) {
    int e = blockIdx.x * 256 + threadIdx.x;
    if (e >= NE) return;
    int seg = trg[e] * 4 + rel[e];
    int pos = atomicAdd(&g_cur[seg], 1);
    g_psrc[pos] = src[e];
}

// ---------------- segment aggregation: contiguous 1KB gathers, packed bf16 out ------------
__global__ void __launch_bounds__(256) edge_agg_kernel() {
    int gw = (blockIdx.x * blockDim.x + threadIdx.x) >> 5;
    int lane = threadIdx.x & 31;
    if (gw >= NSEG) return;
    int seg = gw;
    int tg = seg >> 2, r = seg & 3;
    int beg = g_off[seg], end = g_off[seg + 1];

    float4 st4 = *reinterpret_cast<const float4*>(g_strg + (size_t)tg * 16 + r * 4);
    float strg_h[4] = {st4.x, st4.y, st4.z, st4.w};
    float m_h[4];
#pragma unroll
    for (int h = 0; h < 4; h++) m_h[h] = fdec(g_m_u[r * 4 + h]);

    float num0[4] = {0.f, 0.f, 0.f, 0.f};
    float num1[4] = {0.f, 0.f, 0.f, 0.f};
    float den[4]  = {0.f, 0.f, 0.f, 0.f};

    for (int i = beg; i < end; i++) {
        int s = g_psrc[i];
        const float* pb = g_ps + (size_t)s * CTOT + r * 256;   // contiguous [h][64]
        float4 sp4 = *reinterpret_cast<const float4*>(g_ssrc + (size_t)s * 16 + r * 4);
        float sv[4] = {sp4.x, sp4.y, sp4.z, sp4.w};
#pragma unroll
        for (int h = 0; h < 4; h++) {
            float v = sv[h] + strg_h[h];
            v = (v > 0.f) ? v : 0.2f * v;
            float ex = expf(v - m_h[h]);
            den[h] += ex;
            const float* pp = pb + h * 64;
            num0[h] = fmaf(ex, pp[lane],      num0[h]);
            num1[h] = fmaf(ex, pp[lane + 32], num1[h]);
        }
    }
#pragma unroll
    for (int h = 0; h < 4; h++) {
        float inv = 1.f / (den[h] + 1e-16f);
        unsigned* ag = g_aggp + ((size_t)seg * 4 + h) * 64;
        __nv_bfloat16 hi, lo;
        bsplit(num0[h] * inv, hi, lo); ag[lane]      = bpack(hi, lo);
        bsplit(num1[h] * inv, hi, lo); ag[lane + 32] = bpack(hi, lo);
    }
}

// ---------------- fused node kernel with tensor-core MLP ----------------
#define NS 200
#define NODE2_SMEM (128*NS*2*2 + 64*NS*2*2 + (64+64+64+128+128+32)*4)

__device__ __forceinline__ void mlp_layer(const __nv_bfloat16* __restrict__ Ain,
                                          const __nv_bfloat16* __restrict__ Wm,
                                          const float* __restrict__ bs,
                                          __nv_bfloat16* __restrict__ Hout, int t) {
    int lane = t & 31, w = t >> 5;
    int wm = w >> 2, wn = w & 3;
    int g = lane >> 2, tg = lane & 3;
    float acc[4][2][4];
#pragma unroll
    for (int i = 0; i < 4; i++)
#pragma unroll
        for (int j = 0; j < 2; j++)
#pragma unroll
            for (int q = 0; q < 4; q++) acc[i][j][q] = 0.f;

#pragma unroll
    for (int ks = 0; ks < 12; ks++) {
        int kk = ks * 16;
        unsigned af[4][4], bf_[2][2];
#pragma unroll
        for (int mt = 0; mt < 4; mt++) {
            const __nv_bfloat16* ap = Ain + (wm * 64 + mt * 16 + g) * NS + kk + tg * 2;
            af[mt][0] = *reinterpret_cast<const unsigned*>(ap);
            af[mt][1] = *reinterpret_cast<const unsigned*>(ap + 8 * NS);
            af[mt][2] = *reinterpret_cast<const unsigned*>(ap + 8);
            af[mt][3] = *reinterpret_cast<const unsigned*>(ap + 8 * NS + 8);
        }
#pragma unroll
        for (int nt = 0; nt < 2; nt++) {
            const __nv_bfloat16* bp = Wm + (wn * 16 + nt * 8 + g) * NS + kk + tg * 2;
            bf_[nt][0] = *reinterpret_cast<const unsigned*>(bp);
            bf_[nt][1] = *reinterpret_cast<const unsigned*>(bp + 8);
        }
#pragma unroll
        for (int mt = 0; mt < 4; mt++)
#pragma unroll
            for (int nt = 0; nt < 2; nt++)
                mma_bf16(acc[mt][nt], af[mt][0], af[mt][1], af[mt][2], af[mt][3],
                         bf_[nt][0], bf_[nt][1]);
    }
    __syncthreads();
#pragma unroll
    for (int mt = 0; mt < 4; mt++)
#pragma unroll
        for (int nt = 0; nt < 2; nt++) {
            int row = wm * 64 + mt * 16 + g;
            int col = wn * 16 + nt * 8 + tg * 2;
#pragma unroll
            for (int q = 0; q < 4; q++) {
                int rr = row + ((q >> 1) ? 8 : 0);
                int cc = col + (q & 1);
                float h = fmaxf(acc[mt][nt][q] + bs[cc], 0.f);
                __nv_bfloat16 hi, lo; bsplit(h, hi, lo);
                Hout[rr * NS + cc] = hi;
                Hout[rr * NS + 64 + cc] = lo;
                Hout[rr * NS + 128 + cc] = hi;
            }
        }
    __syncthreads();
}

__global__ void __launch_bounds__(256) node2_kernel(
        const float* __restrict__ W1, const float* __restrict__ b1,
        const float* __restrict__ W2, const float* __restrict__ b2,
        const float* __restrict__ W3, const float* __restrict__ b3,
        const float* __restrict__ bias, const float* __restrict__ gamma,
        const float* __restrict__ beta, float* __restrict__ out) {
    extern __shared__ char nsm[];
    __nv_bfloat16* Asp = reinterpret_cast<__nv_bfloat16*>(nsm);
    __nv_bfloat16* Hsp = Asp + 128 * NS;
    __nv_bfloat16* W1s = Hsp + 128 * NS;
    __nv_bfloat16* W2s = W1s + 64 * NS;
    float* W3s  = reinterpret_cast<float*>(W2s + 64 * NS);
    float* b1s  = W3s + 64;
    float* b2s  = b1s + 64;
    float* scs  = b2s + 64;
    float* alps = scs + 128;
    float* red  = alps + 128;

    int t = threadIdx.x;
    int node0 = blockIdx.x * 8;

    for (int idx = t; idx < 4096; idx += 256) {
        int n_ = idx >> 6, k_ = idx & 63;
        __nv_bfloat16 hi, lo;
        bsplit(W1[idx], hi, lo);
        W1s[n_ * NS + k_] = hi; W1s[n_ * NS + 64 + k_] = hi; W1s[n_ * NS + 128 + k_] = lo;
        bsplit(W2[idx], hi, lo);
        W2s[n_ * NS + k_] = hi; W2s[n_ * NS + 64 + k_] = hi; W2s[n_ * NS + 128 + k_] = lo;
    }
    if (t < 64) { W3s[t] = W3[t]; b1s[t] = b1[t]; b2s[t] = b2[t]; }

    // load packed agg; Asp row = ln*16 + h*4 + r, layout [hi | lo | hi]
    for (int idx = t; idx < 8192; idx += 256) {
        int row = idx >> 6, f = idx & 63;
        int ln = row >> 4, p = row & 15, h = p >> 2, r = p & 3;
        int n = node0 + ln;
        unsigned u = g_aggp[(((size_t)n * 4 + r) * 4 + h) * 64 + f];
        __nv_bfloat16 hi = __ushort_as_bfloat16((unsigned short)(u & 0xffffu));
        __nv_bfloat16 lo = __ushort_as_bfloat16((unsigned short)(u >> 16));
        Asp[row * NS + f] = hi; Asp[row * NS + 64 + f] = lo; Asp[row * NS + 128 + f] = hi;
    }
    __syncthreads();

    mlp_layer(Asp, W1s, b1s, Hsp, t);
    mlp_layer(Hsp, W2s, b2s, Hsp, t);

    if (t < 128) {
        float sacc = b3[0];
        const __nv_bfloat16* hp = Hsp + t * NS;
#pragma unroll
        for (int j = 0; j < 64; j++) {
            float hv = __bfloat162float(hp[j]) + __bfloat162float(hp[64 + j]);
            sacc = fmaf(hv, W3s[j], sacc);
        }
        float sp = (sacc > 20.f) ? sacc : log1pf(expf(sacc));
        scs[t] = sacc * tanhf(sp);
    }
    __syncthreads();

    if (t < 32) {
        int base = (t >> 2) * 16 + (t & 3) * 4;
        float mx = -1e30f;
#pragma unroll
        for (int r = 0; r < 4; r++) mx = fmaxf(mx, scs[base + r]);
        float ev[4], ssum = 0.f;
#pragma unroll
        for (int r = 0; r < 4; r++) { ev[r] = expf(scs[base + r] - mx); ssum += ev[r]; }
#pragma unroll
        for (int r = 0; r < 4; r++) alps[base + r] = ev[r] / ssum;
    }
    __syncthreads();

    int hh = t >> 6, f = t & 63;
    int wid = t >> 5, lane = t & 31;
#pragma unroll 1
    for (int s = 0; s < 8; s++) {
        int n = node0 + s;
        int rb = s * 16 + hh * 4;
        float o = 0.f;
#pragma unroll
        for (int r = 0; r < 4; r++) {
            const __nv_bfloat16* ap = Asp + (rb + r) * NS;
            float a = __bfloat162float(ap[f]) + __bfloat162float(ap[64 + f]);
            o = fmaf(a, alps[rb + r], o);
        }
        o += g_ps[(size_t)n * CTOT + CPROJ + t];
        o += bias[t];
        o = (o > 0.f) ? o : expm1f(o);

        float s1 = o, s2 = o * o;
#pragma unroll
        for (int off = 16; off > 0; off >>= 1) {
            s1 += __shfl_down_sync(0xffffffffu, s1, off);
            s2 += __shfl_down_sync(0xffffffffu, s2, off);
        }
        if (lane == 0) { red[wid] = s1; red[8 + wid] = s2; }
        __syncthreads();
        if (t == 0) {
            float S1 = 0.f, S2 = 0.f;
#pragma unroll
            for (int w = 0; w < 8; w++) { S1 += red[w]; S2 += red[8 + w]; }
            float mu = S1 * (1.f / 256.f);
            float var = S2 * (1.f / 256.f) - mu * mu;
            red[16] = mu;
            red[17] = rsqrtf(var + 1e-5f);
        }
        __syncthreads();
        float mu = red[16], rstd = red[17];
        out[(size_t)n * 256 + t] = (o - mu) * rstd * gamma[t] + beta[t];
        __syncthreads();
    }
}

// ---------------- launch ----------------
extern "C" void kernel_launch(void* const* d_in, const int* in_sizes, int n_in,
                              void* d_out, int out_size) {
    const float* x         = (const float*)d_in[0];
    const int*   src       = (const int*)d_in[1];
    const int*   trg       = (const int*)d_in[2];
    const int*   rel       = (const int*)d_in[3];
    // d_in[4] = node_to_graph_map (unused)
    const float* W_proj    = (const float*)d_in[5];
    const float* score_src = (const float*)d_in[6];
    const float* score_trg = (const float*)d_in[7];
    const float* W1        = (const float*)d_in[8];
    const float* b1        = (const float*)d_in[9];
    const float* W2        = (const float*)d_in[10];
    const float* b2        = (const float*)d_in[11];
    const float* W3        = (const float*)d_in[12];
    const float* b3        = (const float*)d_in[13];
    const float* W_skip    = (const float*)d_in[14];
    const float* bias      = (const float*)d_in[15];
    const float* gamma     = (const float*)d_in[16];
    const float* beta      = (const float*)d_in[17];
    float* out = (float*)d_out;

    cudaFuncSetAttribute(node2_kernel, cudaFuncAttributeMaxDynamicSharedMemorySize, NODE2_SMEM);

    prep_wext_kernel<<<(CTOT * FIN + 511) / 512, 512>>>(W_proj, W_skip);
    zero_kernel<<<784, 256>>>();

    dim3 ggrid(CTOT / 128, (NN + 127) / 128);
    gemm_bf16_kernel<<<ggrid, 256>>>(x, score_src, score_trg);

    int eb = (NE + 255) / 256;
    edge1_kernel<<<eb, 256>>>(src, trg, rel);

    // counting sort by (trg, rel)
    hist_kernel<<<eb, 256>>>(trg, rel);
    scan1_kernel<<<NB1, 1024>>>();
    scan2_kernel<<<1, 256>>>();
    scan3_kernel<<<NB1, 1024>>>();
    scatter_kernel<<<eb, 256>>>(src, trg, rel);

    // atomic-free aggregation
    edge_agg_kernel<<<(NSEG * 32 + 255) / 256, 256>>>();

    node2_kernel<<<NN / 8, 256, NODE2_SMEM>>>(W1, b1, W2, b2, W3, b3, bias, gamma, beta, out);
}

// round 13
// speedup vs baseline: 1.0547x; 1.0547x over previous
#include <cuda_runtime.h>
#include <cuda_bf16.h>
#include <math.h>

// Problem constants
#define NN     50000
#define FIN    256
#define NH     4
#define NR     4
#define FF     64
#define NE     500000
#define CPROJ  1024          // NH*NR*FF
#define CTOT   1280          // CPROJ + NH*FF (skip)
#define NSEG   (NN * NR)     // 200000 (trg, rel) segments
#define NB1    ((NSEG + 1023) / 1024)   // 196 scan blocks

// ---------------- scratch (device globals; no allocation allowed) ----------------
// proj layout PERMUTED: col = r*256 + h*64 + f   (skip still at cols 1024..1279, h*64+f)
__device__ float         g_ps[(size_t)NN * CTOT];
__device__ unsigned      g_aggp[(size_t)NSEG * NH * FF];   // packed bf16 (hi lo) per value
__device__ float         g_ssrc[(size_t)NN * NH * NR];     // [n*16 + r*4 + h]
__device__ float         g_strg[(size_t)NN * NH * NR];
__device__ unsigned      g_m_u[NR * NH];                   // index q = r*4 + h
__device__ __nv_bfloat16 g_aext[(size_t)NN * 512];         // [n][512] = [x_hi(256) | x_lo(256)]
__device__ __nv_bfloat16 g_bext[(size_t)CTOT * 512];       // [c'][512] = [W_hi | W_lo]
// edge sort scratch
__device__ int           g_cnt[NSEG];
__device__ int           g_off[NSEG + 1];
__device__ int           g_cur[NSEG];
__device__ int           g_bsum[256];
__device__ int           g_psrc[NE];                       // src[], permuted by segment

// ---------------- helpers ----------------
__device__ __forceinline__ unsigned fenc(float f) {
    unsigned u = __float_as_uint(f);
    return (u & 0x80000000u) ? ~u : (u | 0x80000000u);
}
__device__ __forceinline__ float fdec(unsigned u) {
    return (u & 0x80000000u) ? __uint_as_float(u & 0x7fffffffu) : __uint_as_float(~u);
}
__device__ __forceinline__ void bsplit(float w, __nv_bfloat16& hi, __nv_bfloat16& lo) {
    hi = __float2bfloat16(w);
    lo = __float2bfloat16(w - __bfloat162float(hi));
}
__device__ __forceinline__ unsigned bpack(__nv_bfloat16 h, __nv_bfloat16 l) {
    return ((unsigned)__bfloat16_as_ushort(l) << 16) | (unsigned)__bfloat16_as_ushort(h);
}
__device__ __forceinline__ void mma_bf16(float* c, unsigned a0, unsigned a1, unsigned a2,
                                         unsigned a3, unsigned b0, unsigned b1) {
    asm volatile(
        "mma.sync.aligned.m16n8k16.row.col.f32.bf16.bf16.f32 "
        "{%0,%1,%2,%3}, {%4,%5,%6,%7}, {%8,%9}, {%0,%1,%2,%3};\n"
        : "+f"(c[0]), "+f"(c[1]), "+f"(c[2]), "+f"(c[3])
        : "r"(a0), "r"(a1), "r"(a2), "r"(a3), "r"(b0), "r"(b1));
}
__device__ __forceinline__ void ldsm4(unsigned& r0, unsigned& r1, unsigned& r2, unsigned& r3,
                                      const void* p) {
    unsigned addr = (unsigned)__cvta_generic_to_shared(p);
    asm volatile("ldmatrix.sync.aligned.m8n8.x4.shared.b16 {%0,%1,%2,%3}, [%4];\n"
                 : "=r"(r0), "=r"(r1), "=r"(r2), "=r"(r3) : "r"(addr));
}

// ---------------- prep kernels ----------------
__global__ void prep_wext_kernel(const float* __restrict__ Wp, const float* __restrict__ Ws) {
    int idx = blockIdx.x * blockDim.x + threadIdx.x;
    if (idx >= CTOT * FIN) return;
    int c = idx >> 8, k = idx & 255;
    float w; int c2;
    if (c < CPROJ) {
        w = Wp[idx];
        int h = c >> 8, r = (c >> 6) & 3, f = c & 63;
        c2 = r * 256 + h * 64 + f;          // permuted: [r][h][f]
    } else {
        w = Ws[(c - CPROJ) * FIN + k];
        c2 = c;
    }
    __nv_bfloat16 hi, lo; bsplit(w, hi, lo);
    size_t b = (size_t)c2 * 512;
    g_bext[b + k] = hi; g_bext[b + 256 + k] = lo;
}

__global__ void prep_aext_kernel(const float* __restrict__ x) {
    int idx = blockIdx.x * blockDim.x + threadIdx.x;
    int tot = NN * FIN;
    for (; idx < tot; idx += gridDim.x * blockDim.x) {
        int n = idx >> 8, k = idx & 255;
        float w = x[idx];
        __nv_bfloat16 hi, lo; bsplit(w, hi, lo);
        size_t b = (size_t)n * 512;
        g_aext[b + k] = hi; g_aext[b + 256 + k] = lo;
    }
}

// ---------------- zero small scratch ----------------
__global__ void zero_kernel() {
    int idx = blockIdx.x * blockDim.x + threadIdx.x;
    for (int i = idx; i < NSEG; i += gridDim.x * blockDim.x) g_cnt[i] = 0;
    if (idx < NR * NH) g_m_u[idx] = 0u;
}

// ---------------- K2: bf16 TC GEMM (R7 structure) + permuted B + fused scores ----------
// C[N,1280] = x[N,256] @ Wcat^T via split-bf16:  hi*hi + hi*lo + lo*hi
#define GSTR 40   // smem row stride in halves (80B) — conflict-free ldmatrix
__global__ void __launch_bounds__(256) gemm_bf16_kernel(const float* __restrict__ sv_src,
                                                        const float* __restrict__ sv_trg) {
    __shared__ __nv_bfloat16 Ah[128 * GSTR];
    __shared__ __nv_bfloat16 Al[128 * GSTR];
    __shared__ __nv_bfloat16 Bh[128 * GSTR];
    __shared__ __nv_bfloat16 Bl[128 * GSTR];
    __shared__ float sred[512];

    int t = threadIdx.x;
    int lane = t & 31, w = t >> 5;
    int wm = w >> 2, wn = w & 3;           // wm 0..1 (64 rows), wn 0..3 (32 cols)
    int g = lane >> 2, tg = lane & 3;
    int row0 = blockIdx.y * 128;
    int col0 = blockIdx.x * 128;

    float acc[4][4][4];
#pragma unroll
    for (int i = 0; i < 4; i++)
#pragma unroll
        for (int j = 0; j < 4; j++)
#pragma unroll
            for (int q = 0; q < 4; q++) acc[i][j][q] = 0.f;

    // load geometry: thread covers rows r0v and r0v+64 of each 128x32 tile
    int r0v = t >> 2;                 // 0..63
    int kcv = (t & 3) * 8;            // 0,8,16,24

    int fr = lane & 15;
    int fcb = (lane >> 4) * 8;

    for (int c = 0; c < 8; c++) {
        int k0 = c * 32;
        int ga0 = row0 + r0v, ga1 = row0 + r0v + 64;
        bool p0 = ga0 < NN, p1 = ga1 < NN;
        const __nv_bfloat16* ap0 = g_aext + (size_t)(p0 ? ga0 : 0) * 512 + k0 + kcv;
        const __nv_bfloat16* ap1 = g_aext + (size_t)(p1 ? ga1 : 0) * 512 + k0 + kcv;
        const __nv_bfloat16* bp0 = g_bext + (size_t)(col0 + r0v) * 512 + k0 + kcv;
        const __nv_bfloat16* bp1 = g_bext + (size_t)(col0 + r0v + 64) * 512 + k0 + kcv;
        float4 z = make_float4(0.f, 0.f, 0.f, 0.f);
        float4 ah0 = p0 ? *reinterpret_cast<const float4*>(ap0)       : z;
        float4 al0 = p0 ? *reinterpret_cast<const float4*>(ap0 + 256) : z;
        float4 ah1 = p1 ? *reinterpret_cast<const float4*>(ap1)       : z;
        float4 al1 = p1 ? *reinterpret_cast<const float4*>(ap1 + 256) : z;
        float4 bh0 = *reinterpret_cast<const float4*>(bp0);
        float4 bl0 = *reinterpret_cast<const float4*>(bp0 + 256);
        float4 bh1 = *reinterpret_cast<const float4*>(bp1);
        float4 bl1 = *reinterpret_cast<const float4*>(bp1 + 256);
        __syncthreads();
        *reinterpret_cast<float4*>(Ah + r0v * GSTR + kcv)        = ah0;
        *reinterpret_cast<float4*>(Ah + (r0v + 64) * GSTR + kcv) = ah1;
        *reinterpret_cast<float4*>(Al + r0v * GSTR + kcv)        = al0;
        *reinterpret_cast<float4*>(Al + (r0v + 64) * GSTR + kcv) = al1;
        *reinterpret_cast<float4*>(Bh + r0v * GSTR + kcv)        = bh0;
        *reinterpret_cast<float4*>(Bh + (r0v + 64) * GSTR + kcv) = bh1;
        *reinterpret_cast<float4*>(Bl + r0v * GSTR + kcv)        = bl0;
        *reinterpret_cast<float4*>(Bl + (r0v + 64) * GSTR + kcv) = bl1;
        __syncthreads();

#pragma unroll
        for (int kk = 0; kk < 32; kk += 16) {
            int fc = kk + fcb;
            unsigned bhf[2][4], blf[2][4];
#pragma unroll
            for (int np = 0; np < 2; np++) {
                int n = wn * 32 + np * 16 + fr;
                ldsm4(bhf[np][0], bhf[np][1], bhf[np][2], bhf[np][3], Bh + n * GSTR + fc);
                ldsm4(blf[np][0], blf[np][1], blf[np][2], blf[np][3], Bl + n * GSTR + fc);
            }
            // pass 1+2: A_hi against B_hi and B_lo
#pragma unroll
            for (int mt = 0; mt < 4; mt++) {
                int r = wm * 64 + mt * 16 + fr;
                unsigned a0, a1, a2, a3;
                ldsm4(a0, a1, a2, a3, Ah + r * GSTR + fc);
#pragma unroll
                for (int nt = 0; nt < 4; nt++) {
                    int np = nt >> 1, sel = nt & 1;
                    mma_bf16(acc[mt][nt], a0, a1, a2, a3, bhf[np][sel], bhf[np][sel + 2]);
                    mma_bf16(acc[mt][nt], a0, a1, a2, a3, blf[np][sel], blf[np][sel + 2]);
                }
            }
            // pass 3: A_lo against B_hi
#pragma unroll
            for (int mt = 0; mt < 4; mt++) {
                int r = wm * 64 + mt * 16 + fr;
                unsigned a0, a1, a2, a3;
                ldsm4(a0, a1, a2, a3, Al + r * GSTR + fc);
#pragma unroll
                for (int nt = 0; nt < 4; nt++) {
                    int np = nt >> 1, sel = nt & 1;
                    mma_bf16(acc[mt][nt], a0, a1, a2, a3, bhf[np][sel], bhf[np][sel + 2]);
                }
            }
        }
    }

    // write proj/skip (permuted layout is whatever g_bext columns encode)
#pragma unroll
    for (int mt = 0; mt < 4; mt++)
#pragma unroll
        for (int nt = 0; nt < 4; nt++) {
            int row = row0 + wm * 64 + mt * 16 + g;
            int col = col0 + wn * 32 + nt * 8 + tg * 2;
            if (row < NN) {
                float2 o = make_float2(acc[mt][nt][0], acc[mt][nt][1]);
                *reinterpret_cast<float2*>(g_ps + (size_t)row * CTOT + col) = o;
            }
            if (row + 8 < NN) {
                float2 o = make_float2(acc[mt][nt][2], acc[mt][nt][3]);
                *reinterpret_cast<float2*>(g_ps + (size_t)(row + 8) * CTOT + col) = o;
            }
        }

    // fused attention-score epilogue (proj columns only; permuted slice q = r*4+h)
    if (col0 < CPROJ) {
        __syncthreads();
        for (int i = t; i < 512; i += 256) sred[i] = 0.f;
        __syncthreads();

        // score vectors are [h][r][f]; permuted column c2 = (r*4+h)*64+f -> un-permute.
        float sv[4][2], tv[4][2];
#pragma unroll
        for (int nt = 0; nt < 4; nt++)
#pragma unroll
            for (int qc = 0; qc < 2; qc++) {
                int c2 = col0 + wn * 32 + nt * 8 + tg * 2 + qc;
                int q = c2 >> 6;
                int rr_ = q >> 2, hh_ = q & 3;
                int corig = (hh_ * 4 + rr_) * 64 + (c2 & 63);
                sv[nt][qc] = sv_src[corig];
                tv[nt][qc] = sv_trg[corig];
            }
        int p_idx = wn >> 1;
#pragma unroll
        for (int mt = 0; mt < 4; mt++) {
            float s0 = 0.f, s1 = 0.f, t0 = 0.f, t1 = 0.f;
#pragma unroll
            for (int nt = 0; nt < 4; nt++)
#pragma unroll
                for (int qc = 0; qc < 2; qc++) {
                    s0 = fmaf(acc[mt][nt][qc],     sv[nt][qc], s0);
                    t0 = fmaf(acc[mt][nt][qc],     tv[nt][qc], t0);
                    s1 = fmaf(acc[mt][nt][2 + qc], sv[nt][qc], s1);
                    t1 = fmaf(acc[mt][nt][2 + qc], tv[nt][qc], t1);
                }
#pragma unroll
            for (int off = 1; off < 4; off <<= 1) {
                s0 += __shfl_xor_sync(0xffffffffu, s0, off);
                t0 += __shfl_xor_sync(0xffffffffu, t0, off);
                s1 += __shfl_xor_sync(0xffffffffu, s1, off);
                t1 += __shfl_xor_sync(0xffffffffu, t1, off);
            }
            if (tg == 0) {
                int r0 = wm * 64 + mt * 16 + g;
                atomicAdd(&sred[r0 * 4 + p_idx],           s0);
                atomicAdd(&sred[r0 * 4 + 2 + p_idx],       t0);
                atomicAdd(&sred[(r0 + 8) * 4 + p_idx],     s1);
                atomicAdd(&sred[(r0 + 8) * 4 + 2 + p_idx], t1);
            }
        }
        __syncthreads();
        int p0s = col0 >> 6;   // permuted slice base (q index)
        for (int i = t; i < 512; i += 256) {
            int row = i >> 2, j = i & 3;
            int n = row0 + row;
            if (n < NN) {
                float vval = sred[i];
                int p = p0s + (j & 1);
                if (j < 2) g_ssrc[n * 16 + p] = vval;
                else       g_strg[n * 16 + p] = vval;
            }
        }
    }
}

// ---------------- edge pass 1: per-(rel,head) max (q = r*4+h) ----------------
__global__ void __launch_bounds__(256) edge1_kernel(const int* __restrict__ src,
                                                    const int* __restrict__ trg,
                                                    const int* __restrict__ rel) {
    __shared__ unsigned sm[16];
    int t = threadIdx.x;
    if (t < 16) sm[t] = 0u;
    __syncthreads();
    int e = blockIdx.x * 256 + t;
    if (e < NE) {
        int r = rel[e];
        float4 a = *reinterpret_cast<const float4*>(g_ssrc + (size_t)src[e] * 16 + r * 4);
        float4 b = *reinterpret_cast<const float4*>(g_strg + (size_t)trg[e] * 16 + r * 4);
        float vv[4] = {a.x + b.x, a.y + b.y, a.z + b.z, a.w + b.w};
#pragma unroll
        for (int h = 0; h < 4; h++) {
            float v = (vv[h] > 0.f) ? vv[h] : 0.2f * vv[h];
            atomicMax(&sm[r * 4 + h], fenc(v));
        }
    }
    __syncthreads();
    if (t < 16 && sm[t] != 0u) atomicMax(&g_m_u[t], sm[t]);
}

// ---------------- counting sort: hist / scan x3 / scatter ----------------
__global__ void hist_kernel(const int* __restrict__ trg, const int* __restrict__ rel) {
    int e = blockIdx.x * 256 + threadIdx.x;
    if (e < NE) atomicAdd(&g_cnt[trg[e] * 4 + rel[e]], 1);
}

__global__ void __launch_bounds__(1024) scan1_kernel() {
    __shared__ int sd[1024];
    int t = threadIdx.x;
    int i = blockIdx.x * 1024 + t;
    int v = (i < NSEG) ? g_cnt[i] : 0;
    sd[t] = v;
    __syncthreads();
#pragma unroll
    for (int off = 1; off < 1024; off <<= 1) {
        int u = (t >= off) ? sd[t - off] : 0;
        __syncthreads();
        sd[t] += u;
        __syncthreads();
    }
    if (i < NSEG) g_off[i] = sd[t] - v;
    if (t == 1023) g_bsum[blockIdx.x] = sd[t];
}

__global__ void __launch_bounds__(256) scan2_kernel() {
    __shared__ int sd[256];
    int t = threadIdx.x;
    int v = (t < NB1) ? g_bsum[t] : 0;
    sd[t] = v;
    __syncthreads();
#pragma unroll
    for (int off = 1; off < 256; off <<= 1) {
        int u = (t >= off) ? sd[t - off] : 0;
        __syncthreads();
        sd[t] += u;
        __syncthreads();
    }
    if (t < NB1) g_bsum[t] = sd[t] - v;
    if (t == 0) g_off[NSEG] = NE;
}

__global__ void __launch_bounds__(1024) scan3_kernel() {
    int i = blockIdx.x * 1024 + threadIdx.x;
    if (i < NSEG) {
        int o = g_off[i] + g_bsum[blockIdx.x];
        g_off[i] = o;
        g_cur[i] = o;
    }
}

__global__ void scatter_kernel(const int* __restrict__ src, const int* __restrict__ trg,
                               const int* __restrict__ rel) {
    int e = blockIdx.x * 256 + threadIdx.x;
    if (e >= NE) return;
    int seg = trg[e] * 4 + rel[e];
    int pos = atomicAdd(&g_cur[seg], 1);
    g_psrc[pos] = src[e];
}

// ---------------- segment aggregation: contiguous 1KB gathers, packed bf16 out ------------
__global__ void __launch_bounds__(256) edge_agg_kernel() {
    int gw = (blockIdx.x * blockDim.x + threadIdx.x) >> 5;
    int lane = threadIdx.x & 31;
    if (gw >= NSEG) return;
    int seg = gw;
    int tg = seg >> 2, r = seg & 3;
    int beg = g_off[seg], end = g_off[seg + 1];

    float4 st4 = *reinterpret_cast<const float4*>(g_strg + (size_t)tg * 16 + r * 4);
    float strg_h[4] = {st4.x, st4.y, st4.z, st4.w};
    float m_h[4];
#pragma unroll
    for (int h = 0; h < 4; h++) m_h[h] = fdec(g_m_u[r * 4 + h]);

    float num0[4] = {0.f, 0.f, 0.f, 0.f};
    float num1[4] = {0.f, 0.f, 0.f, 0.f};
    float den[4]  = {0.f, 0.f, 0.f, 0.f};

    for (int i = beg; i < end; i++) {
        int s = g_psrc[i];
        const float* pb = g_ps + (size_t)s * CTOT + r * 256;   // contiguous [h][64]
        float4 sp4 = *reinterpret_cast<const float4*>(g_ssrc + (size_t)s * 16 + r * 4);
        float sv[4] = {sp4.x, sp4.y, sp4.z, sp4.w};
#pragma unroll
        for (int h = 0; h < 4; h++) {
            float v = sv[h] + strg_h[h];
            v = (v > 0.f) ? v : 0.2f * v;
            float ex = expf(v - m_h[h]);
            den[h] += ex;
            const float* pp = pb + h * 64;
            num0[h] = fmaf(ex, pp[lane],      num0[h]);
            num1[h] = fmaf(ex, pp[lane + 32], num1[h]);
        }
    }
#pragma unroll
    for (int h = 0; h < 4; h++) {
        float inv = 1.f / (den[h] + 1e-16f);
        unsigned* ag = g_aggp + ((size_t)seg * 4 + h) * 64;
        __nv_bfloat16 hi, lo;
        bsplit(num0[h] * inv, hi, lo); ag[lane]      = bpack(hi, lo);
        bsplit(num1[h] * inv, hi, lo); ag[lane + 32] = bpack(hi, lo);
    }
}

// ---------------- fused node kernel with tensor-core MLP ----------------
#define NS 200
#define NODE2_SMEM (128*NS*2*2 + 64*NS*2*2 + (64+64+64+128+128+32)*4)

__device__ __forceinline__ void mlp_layer(const __nv_bfloat16* __restrict__ Ain,
                                          const __nv_bfloat16* __restrict__ Wm,
                                          const float* __restrict__ bs,
                                          __nv_bfloat16* __restrict__ Hout, int t) {
    int lane = t & 31, w = t >> 5;
    int wm = w >> 2, wn = w & 3;
    int g = lane >> 2, tg = lane & 3;
    float acc[4][2][4];
#pragma unroll
    for (int i = 0; i < 4; i++)
#pragma unroll
        for (int j = 0; j < 2; j++)
#pragma unroll
            for (int q = 0; q < 4; q++) acc[i][j][q] = 0.f;

#pragma unroll
    for (int ks = 0; ks < 12; ks++) {
        int kk = ks * 16;
        unsigned af[4][4], bf_[2][2];
#pragma unroll
        for (int mt = 0; mt < 4; mt++) {
            const __nv_bfloat16* ap = Ain + (wm * 64 + mt * 16 + g) * NS + kk + tg * 2;
            af[mt][0] = *reinterpret_cast<const unsigned*>(ap);
            af[mt][1] = *reinterpret_cast<const unsigned*>(ap + 8 * NS);
            af[mt][2] = *reinterpret_cast<const unsigned*>(ap + 8);
            af[mt][3] = *reinterpret_cast<const unsigned*>(ap + 8 * NS + 8);
        }
#pragma unroll
        for (int nt = 0; nt < 2; nt++) {
            const __nv_bfloat16* bp = Wm + (wn * 16 + nt * 8 + g) * NS + kk + tg * 2;
            bf_[nt][0] = *reinterpret_cast<const unsigned*>(bp);
            bf_[nt][1] = *reinterpret_cast<const unsigned*>(bp + 8);
        }
#pragma unroll
        for (int mt = 0; mt < 4; mt++)
#pragma unroll
            for (int nt = 0; nt < 2; nt++)
                mma_bf16(acc[mt][nt], af[mt][0], af[mt][1], af[mt][2], af[mt][3],
                         bf_[nt][0], bf_[nt][1]);
    }
    __syncthreads();
#pragma unroll
    for (int mt = 0; mt < 4; mt++)
#pragma unroll
        for (int nt = 0; nt < 2; nt++) {
            int row = wm * 64 + mt * 16 + g;
            int col = wn * 16 + nt * 8 + tg * 2;
#pragma unroll
            for (int q = 0; q < 4; q++) {
                int rr = row + ((q >> 1) ? 8 : 0);
                int cc = col + (q & 1);
                float h = fmaxf(acc[mt][nt][q] + bs[cc], 0.f);
                __nv_bfloat16 hi, lo; bsplit(h, hi, lo);
                Hout[rr * NS + cc] = hi;
                Hout[rr * NS + 64 + cc] = lo;
                Hout[rr * NS + 128 + cc] = hi;
            }
        }
    __syncthreads();
}

__global__ void __launch_bounds__(256) node2_kernel(
        const float* __restrict__ W1, const float* __restrict__ b1,
        const float* __restrict__ W2, const float* __restrict__ b2,
        const float* __restrict__ W3, const float* __restrict__ b3,
        const float* __restrict__ bias, const float* __restrict__ gamma,
        const float* __restrict__ beta, float* __restrict__ out) {
    extern __shared__ char nsm[];
    __nv_bfloat16* Asp = reinterpret_cast<__nv_bfloat16*>(nsm);
    __nv_bfloat16* Hsp = Asp + 128 * NS;
    __nv_bfloat16* W1s = Hsp + 128 * NS;
    __nv_bfloat16* W2s = W1s + 64 * NS;
    float* W3s  = reinterpret_cast<float*>(W2s + 64 * NS);
    float* b1s  = W3s + 64;
    float* b2s  = b1s + 64;
    float* scs  = b2s + 64;
    float* alps = scs + 128;
    float* red  = alps + 128;

    int t = threadIdx.x;
    int node0 = blockIdx.x * 8;

    for (int idx = t; idx < 4096; idx += 256) {
        int n_ = idx >> 6, k_ = idx & 63;
        __nv_bfloat16 hi, lo;
        bsplit(W1[idx], hi, lo);
        W1s[n_ * NS + k_] = hi; W1s[n_ * NS + 64 + k_] = hi; W1s[n_ * NS + 128 + k_] = lo;
        bsplit(W2[idx], hi, lo);
        W2s[n_ * NS + k_] = hi; W2s[n_ * NS + 64 + k_] = hi; W2s[n_ * NS + 128 + k_] = lo;
    }
    if (t < 64) { W3s[t] = W3[t]; b1s[t] = b1[t]; b2s[t] = b2[t]; }

    // load packed agg; Asp row = ln*16 + h*4 + r, layout [hi | lo | hi]
    for (int idx = t; idx < 8192; idx += 256) {
        int row = idx >> 6, f = idx & 63;
        int ln = row >> 4, p = row & 15, h = p >> 2, r = p & 3;
        int n = node0 + ln;
        unsigned u = g_aggp[(((size_t)n * 4 + r) * 4 + h) * 64 + f];
        __nv_bfloat16 hi = __ushort_as_bfloat16((unsigned short)(u & 0xffffu));
        __nv_bfloat16 lo = __ushort_as_bfloat16((unsigned short)(u >> 16));
        Asp[row * NS + f] = hi; Asp[row * NS + 64 + f] = lo; Asp[row * NS + 128 + f] = hi;
    }
    __syncthreads();

    mlp_layer(Asp, W1s, b1s, Hsp, t);
    mlp_layer(Hsp, W2s, b2s, Hsp, t);

    if (t < 128) {
        float sacc = b3[0];
        const __nv_bfloat16* hp = Hsp + t * NS;
#pragma unroll
        for (int j = 0; j < 64; j++) {
            float hv = __bfloat162float(hp[j]) + __bfloat162float(hp[64 + j]);
            sacc = fmaf(hv, W3s[j], sacc);
        }
        float sp = (sacc > 20.f) ? sacc : log1pf(expf(sacc));
        scs[t] = sacc * tanhf(sp);
    }
    __syncthreads();

    if (t < 32) {
        int base = (t >> 2) * 16 + (t & 3) * 4;
        float mx = -1e30f;
#pragma unroll
        for (int r = 0; r < 4; r++) mx = fmaxf(mx, scs[base + r]);
        float ev[4], ssum = 0.f;
#pragma unroll
        for (int r = 0; r < 4; r++) { ev[r] = expf(scs[base + r] - mx); ssum += ev[r]; }
#pragma unroll
        for (int r = 0; r < 4; r++) alps[base + r] = ev[r] / ssum;
    }
    __syncthreads();

    int hh = t >> 6, f = t & 63;
    int wid = t >> 5, lane = t & 31;
#pragma unroll 1
    for (int s = 0; s < 8; s++) {
        int n = node0 + s;
        int rb = s * 16 + hh * 4;
        float o = 0.f;
#pragma unroll
        for (int r = 0; r < 4; r++) {
            const __nv_bfloat16* ap = Asp + (rb + r) * NS;
            float a = __bfloat162float(ap[f]) + __bfloat162float(ap[64 + f]);
            o = fmaf(a, alps[rb + r], o);
        }
        o += g_ps[(size_t)n * CTOT + CPROJ + t];
        o += bias[t];
        o = (o > 0.f) ? o : expm1f(o);

        float s1 = o, s2 = o * o;
#pragma unroll
        for (int off = 16; off > 0; off >>= 1) {
            s1 += __shfl_down_sync(0xffffffffu, s1, off);
            s2 += __shfl_down_sync(0xffffffffu, s2, off);
        }
        if (lane == 0) { red[wid] = s1; red[8 + wid] = s2; }
        __syncthreads();
        if (t == 0) {
            float S1 = 0.f, S2 = 0.f;
#pragma unroll
            for (int w = 0; w < 8; w++) { S1 += red[w]; S2 += red[8 + w]; }
            float mu = S1 * (1.f / 256.f);
            float var = S2 * (1.f / 256.f) - mu * mu;
            red[16] = mu;
            red[17] = rsqrtf(var + 1e-5f);
        }
        __syncthreads();
        float mu = red[16], rstd = red[17];
        out[(size_t)n * 256 + t] = (o - mu) * rstd * gamma[t] + beta[t];
        __syncthreads();
    }
}

// ---------------- launch ----------------
extern "C" void kernel_launch(void* const* d_in, const int* in_sizes, int n_in,
                              void* d_out, int out_size) {
    const float* x         = (const float*)d_in[0];
    const int*   src       = (const int*)d_in[1];
    const int*   trg       = (const int*)d_in[2];
    const int*   rel       = (const int*)d_in[3];
    // d_in[4] = node_to_graph_map (unused)
    const float* W_proj    = (const float*)d_in[5];
    const float* score_src = (const float*)d_in[6];
    const float* score_trg = (const float*)d_in[7];
    const float* W1        = (const float*)d_in[8];
    const float* b1        = (const float*)d_in[9];
    const float* W2        = (const float*)d_in[10];
    const float* b2        = (const float*)d_in[11];
    const float* W3        = (const float*)d_in[12];
    const float* b3        = (const float*)d_in[13];
    const float* W_skip    = (const float*)d_in[14];
    const float* bias      = (const float*)d_in[15];
    const float* gamma     = (const float*)d_in[16];
    const float* beta      = (const float*)d_in[17];
    float* out = (float*)d_out;

    cudaFuncSetAttribute(node2_kernel, cudaFuncAttributeMaxDynamicSharedMemorySize, NODE2_SMEM);

    prep_wext_kernel<<<(CTOT * FIN + 511) / 512, 512>>>(W_proj, W_skip);
    prep_aext_kernel<<<8192, 256>>>(x);
    zero_kernel<<<784, 256>>>();

    dim3 ggrid(CTOT / 128, (NN + 127) / 128);
    gemm_bf16_kernel<<<ggrid, 256>>>(score_src, score_trg);

    int eb = (NE + 255) / 256;
    edge1_kernel<<<eb, 256>>>(src, trg, rel);

    // counting sort by (trg, rel)
    hist_kernel<<<eb, 256>>>(trg, rel);
    scan1_kernel<<<NB1, 1024>>>();
    scan2_kernel<<<1, 256>>>();
    scan3_kernel<<<NB1, 1024>>>();
    scatter_kernel<<<eb, 256>>>(src, trg, rel);

    // atomic-free aggregation
    edge_agg_kernel<<<(NSEG * 32 + 255) / 256, 256>>>();

    node2_kernel<<<NN / 8, 256, NODE2_SMEM>>>(W1, b1, W2, b2, W3, b3, bias, gamma, beta, out);
}

// round 14
// speedup vs baseline: 1.0972x; 1.0403x over previous
#include <cuda_runtime.h>
#include <cuda_bf16.h>
#include <math.h>

// Problem constants
#define NN     50000
#define FIN    256
#define NH     4
#define NR     4
#define FF     64
#define NE     500000
#define CPROJ  1024          // NH*NR*FF
#define CTOT   1280          // CPROJ + NH*FF (skip)
#define NSEG   (NN * NR)     // 200000 (trg, rel) segments
#define NB1    ((NSEG + 1023) / 1024)   // 196 scan blocks

// ---------------- scratch (device globals; no allocation allowed) ----------------
// proj layout PERMUTED: col = r*256 + h*64 + f   (skip still at cols 1024..1279, h*64+f)
__device__ float         g_ps[(size_t)NN * CTOT];
__device__ unsigned      g_aggp[(size_t)NSEG * NH * FF];   // packed bf16 (hi lo) per value
__device__ float         g_ssrc[(size_t)NN * NH * NR];     // [n*16 + r*4 + h]
__device__ float         g_strg[(size_t)NN * NH * NR];
__device__ unsigned      g_m_u[NR * NH];                   // index q = r*4 + h
__device__ __align__(16) __nv_bfloat16 g_aext[(size_t)NN * 512];   // [n][512] = [x_hi | x_lo]
__device__ __align__(16) __nv_bfloat16 g_bext[(size_t)CTOT * 512]; // [c'][512] = [W_hi | W_lo]
__device__ __align__(16) __nv_bfloat16 g_w12[2 * 64 * 192];        // pre-split W1/W2 [hi|hi|lo]
// edge sort scratch
__device__ int           g_cnt[NSEG];
__device__ int           g_off[NSEG + 1];
__device__ int           g_cur[NSEG];
__device__ int           g_bsum[256];
__device__ int           g_psrc[NE];                       // src[], permuted by segment

// ---------------- helpers ----------------
__device__ __forceinline__ unsigned fenc(float f) {
    unsigned u = __float_as_uint(f);
    return (u & 0x80000000u) ? ~u : (u | 0x80000000u);
}
__device__ __forceinline__ float fdec(unsigned u) {
    return (u & 0x80000000u) ? __uint_as_float(u & 0x7fffffffu) : __uint_as_float(~u);
}
__device__ __forceinline__ void bsplit(float w, __nv_bfloat16& hi, __nv_bfloat16& lo) {
    hi = __float2bfloat16(w);
    lo = __float2bfloat16(w - __bfloat162float(hi));
}
__device__ __forceinline__ unsigned bpack(__nv_bfloat16 h, __nv_bfloat16 l) {
    return ((unsigned)__bfloat16_as_ushort(l) << 16) | (unsigned)__bfloat16_as_ushort(h);
}
__device__ __forceinline__ void mma_bf16(float* c, unsigned a0, unsigned a1, unsigned a2,
                                         unsigned a3, unsigned b0, unsigned b1) {
    asm volatile(
        "mma.sync.aligned.m16n8k16.row.col.f32.bf16.bf16.f32 "
        "{%0,%1,%2,%3}, {%4,%5,%6,%7}, {%8,%9}, {%0,%1,%2,%3};\n"
        : "+f"(c[0]), "+f"(c[1]), "+f"(c[2]), "+f"(c[3])
        : "r"(a0), "r"(a1), "r"(a2), "r"(a3), "r"(b0), "r"(b1));
}
__device__ __forceinline__ void ldsm4(unsigned& r0, unsigned& r1, unsigned& r2, unsigned& r3,
                                      const void* p) {
    unsigned addr = (unsigned)__cvta_generic_to_shared(p);
    asm volatile("ldmatrix.sync.aligned.m8n8.x4.shared.b16 {%0,%1,%2,%3}, [%4];\n"
                 : "=r"(r0), "=r"(r1), "=r"(r2), "=r"(r3) : "r"(addr));
}
__device__ __forceinline__ void cp16(void* smem, const void* g, bool pred) {
    unsigned s = (unsigned)__cvta_generic_to_shared(smem);
    int sz = pred ? 16 : 0;
    asm volatile("cp.async.cg.shared.global [%0], [%1], 16, %2;\n" :: "r"(s), "l"(g), "r"(sz));
}
template <int N> __device__ __forceinline__ void cpwait() {
    asm volatile("cp.async.wait_group %0;\n" :: "n"(N) : "memory");
}

// ---------------- prep kernels ----------------
__global__ void prep_wext_kernel(const float* __restrict__ Wp, const float* __restrict__ Ws) {
    int idx = blockIdx.x * blockDim.x + threadIdx.x;
    if (idx >= CTOT * FIN) return;
    int c = idx >> 8, k = idx & 255;
    float w; int c2;
    if (c < CPROJ) {
        w = Wp[idx];
        int h = c >> 8, r = (c >> 6) & 3, f = c & 63;
        c2 = r * 256 + h * 64 + f;          // permuted: [r][h][f]
    } else {
        w = Ws[(c - CPROJ) * FIN + k];
        c2 = c;
    }
    __nv_bfloat16 hi, lo; bsplit(w, hi, lo);
    size_t b = (size_t)c2 * 512;
    g_bext[b + k] = hi; g_bext[b + 256 + k] = lo;
}

__global__ void prep_aext_kernel(const float* __restrict__ x) {
    int idx = blockIdx.x * blockDim.x + threadIdx.x;
    int tot = NN * FIN;
    for (; idx < tot; idx += gridDim.x * blockDim.x) {
        int n = idx >> 8, k = idx & 255;
        float w = x[idx];
        __nv_bfloat16 hi, lo; bsplit(w, hi, lo);
        size_t b = (size_t)n * 512;
        g_aext[b + k] = hi; g_aext[b + 256 + k] = lo;
    }
}

// pre-split node MLP weights into [hi(64) | hi(64) | lo(64)] rows of 192
__global__ void prep_w12_kernel(const float* __restrict__ W1, const float* __restrict__ W2) {
    int idx = blockIdx.x * blockDim.x + threadIdx.x;
    if (idx >= 2 * 64 * 64) return;
    int which = idx >> 12, rem = idx & 4095;
    int n_ = rem >> 6, k_ = rem & 63;
    float w = which ? W2[rem] : W1[rem];
    __nv_bfloat16 hi, lo; bsplit(w, hi, lo);
    int base = which * 64 * 192 + n_ * 192;
    g_w12[base + k_] = hi; g_w12[base + 64 + k_] = hi; g_w12[base + 128 + k_] = lo;
}

// ---------------- zero small scratch ----------------
__global__ void zero_kernel() {
    int idx = blockIdx.x * blockDim.x + threadIdx.x;
    for (int i = idx; i < NSEG; i += gridDim.x * blockDim.x) g_cnt[i] = 0;
    if (idx < NR * NH) g_m_u[idx] = 0u;
}

// ---------------- K2: bf16 TC GEMM — cp.async 2-stage, ldmatrix, fused scores ----------
// C[N,1280] = x[N,256] @ Wcat^T via split-bf16:  hi*hi + hi*lo + lo*hi
#define GSTR  40                        // smem row stride in halves (80B)
#define TILEH (128 * GSTR)              // halves per 128x32 tile
#define TILEB (TILEH * 2)               // 10240 bytes
#define GSMEM (8 * TILEB + 512 * 4)     // 2 stages x 4 tiles + sred = 83968

__global__ void __launch_bounds__(256) gemm_bf16_kernel(const float* __restrict__ sv_src,
                                                        const float* __restrict__ sv_trg) {
    extern __shared__ char gsm[];
    __nv_bfloat16* A0h = reinterpret_cast<__nv_bfloat16*>(gsm);
    __nv_bfloat16* A0l = A0h + TILEH;
    __nv_bfloat16* B0h = A0l + TILEH;
    __nv_bfloat16* B0l = B0h + TILEH;
    __nv_bfloat16* A1h = B0l + TILEH;
    __nv_bfloat16* A1l = A1h + TILEH;
    __nv_bfloat16* B1h = A1l + TILEH;
    __nv_bfloat16* B1l = B1h + TILEH;
    float* sred = reinterpret_cast<float*>(gsm + 8 * TILEB);

    int t = threadIdx.x;
    int lane = t & 31, w = t >> 5;
    int wm = w >> 2, wn = w & 3;           // wm 0..1 (64 rows), wn 0..3 (32 cols)
    int g = lane >> 2, tg = lane & 3;
    int row0 = blockIdx.y * 128;
    int col0 = blockIdx.x * 128;

    float acc[4][4][4];
#pragma unroll
    for (int i = 0; i < 4; i++)
#pragma unroll
        for (int j = 0; j < 4; j++)
#pragma unroll
            for (int q = 0; q < 4; q++) acc[i][j][q] = 0.f;

    int r0v = t >> 2;                 // 0..63
    int kcv = (t & 3) * 8;            // 0,8,16,24
    int fr = lane & 15;
    int fcb = (lane >> 4) * 8;

    int ga0 = row0 + r0v, ga1 = row0 + r0v + 64;
    bool p0 = ga0 < NN, p1 = ga1 < NN;
    const __nv_bfloat16* apA0 = g_aext + (size_t)(p0 ? ga0 : 0) * 512 + kcv;
    const __nv_bfloat16* apA1 = g_aext + (size_t)(p1 ? ga1 : 0) * 512 + kcv;
    const __nv_bfloat16* bpB0 = g_bext + (size_t)(col0 + r0v) * 512 + kcv;
    const __nv_bfloat16* bpB1 = g_bext + (size_t)(col0 + r0v + 64) * 512 + kcv;
    int d0 = r0v * GSTR + kcv;
    int d1 = (r0v + 64) * GSTR + kcv;

    auto issue = [&](int c, __nv_bfloat16* Ah, __nv_bfloat16* Al,
                     __nv_bfloat16* Bh, __nv_bfloat16* Bl) {
        int k0 = c * 32;
        cp16(Ah + d0, apA0 + k0,       p0);
        cp16(Al + d0, apA0 + 256 + k0, p0);
        cp16(Ah + d1, apA1 + k0,       p1);
        cp16(Al + d1, apA1 + 256 + k0, p1);
        cp16(Bh + d0, bpB0 + k0,       true);
        cp16(Bl + d0, bpB0 + 256 + k0, true);
        cp16(Bh + d1, bpB1 + k0,       true);
        cp16(Bl + d1, bpB1 + 256 + k0, true);
        asm volatile("cp.async.commit_group;\n" ::: "memory");
    };

    auto compute = [&](const __nv_bfloat16* Ah, const __nv_bfloat16* Al,
                       const __nv_bfloat16* Bh, const __nv_bfloat16* Bl) {
#pragma unroll
        for (int kk = 0; kk < 32; kk += 16) {
            int fc = kk + fcb;
            unsigned bhf[2][4], blf[2][4];
#pragma unroll
            for (int np = 0; np < 2; np++) {
                int n = wn * 32 + np * 16 + fr;
                ldsm4(bhf[np][0], bhf[np][1], bhf[np][2], bhf[np][3], Bh + n * GSTR + fc);
                ldsm4(blf[np][0], blf[np][1], blf[np][2], blf[np][3], Bl + n * GSTR + fc);
            }
            // A_hi vs B_hi and B_lo
#pragma unroll
            for (int mt = 0; mt < 4; mt++) {
                int r = wm * 64 + mt * 16 + fr;
                unsigned a0, a1, a2, a3;
                ldsm4(a0, a1, a2, a3, Ah + r * GSTR + fc);
#pragma unroll
                for (int nt = 0; nt < 4; nt++) {
                    int np = nt >> 1, sel = nt & 1;
                    mma_bf16(acc[mt][nt], a0, a1, a2, a3, bhf[np][sel], bhf[np][sel + 2]);
                    mma_bf16(acc[mt][nt], a0, a1, a2, a3, blf[np][sel], blf[np][sel + 2]);
                }
            }
            // A_lo vs B_hi
#pragma unroll
            for (int mt = 0; mt < 4; mt++) {
                int r = wm * 64 + mt * 16 + fr;
                unsigned a0, a1, a2, a3;
                ldsm4(a0, a1, a2, a3, Al + r * GSTR + fc);
#pragma unroll
                for (int nt = 0; nt < 4; nt++) {
                    int np = nt >> 1, sel = nt & 1;
                    mma_bf16(acc[mt][nt], a0, a1, a2, a3, bhf[np][sel], bhf[np][sel + 2]);
                }
            }
        }
    };

    issue(0, A0h, A0l, B0h, B0l);
    issue(1, A1h, A1l, B1h, B1l);

#pragma unroll
    for (int c = 0; c < 8; c++) {
        if (c < 7) cpwait<1>(); else cpwait<0>();
        __syncthreads();
        if ((c & 1) == 0) {
            compute(A0h, A0l, B0h, B0l);
            __syncthreads();
            if (c + 2 < 8) issue(c + 2, A0h, A0l, B0h, B0l);
        } else {
            compute(A1h, A1l, B1h, B1l);
            __syncthreads();
            if (c + 2 < 8) issue(c + 2, A1h, A1l, B1h, B1l);
        }
    }

    // write proj/skip
#pragma unroll
    for (int mt = 0; mt < 4; mt++)
#pragma unroll
        for (int nt = 0; nt < 4; nt++) {
            int row = row0 + wm * 64 + mt * 16 + g;
            int col = col0 + wn * 32 + nt * 8 + tg * 2;
            if (row < NN) {
                float2 o = make_float2(acc[mt][nt][0], acc[mt][nt][1]);
                *reinterpret_cast<float2*>(g_ps + (size_t)row * CTOT + col) = o;
            }
            if (row + 8 < NN) {
                float2 o = make_float2(acc[mt][nt][2], acc[mt][nt][3]);
                *reinterpret_cast<float2*>(g_ps + (size_t)(row + 8) * CTOT + col) = o;
            }
        }

    // fused attention-score epilogue (proj columns only; permuted slice q = r*4+h)
    if (col0 < CPROJ) {
        __syncthreads();
        for (int i = t; i < 512; i += 256) sred[i] = 0.f;
        __syncthreads();

        // score vectors are [h][r][f]; permuted column c2 = (r*4+h)*64+f -> un-permute.
        float sv[4][2], tv[4][2];
#pragma unroll
        for (int nt = 0; nt < 4; nt++)
#pragma unroll
            for (int qc = 0; qc < 2; qc++) {
                int c2 = col0 + wn * 32 + nt * 8 + tg * 2 + qc;
                int q = c2 >> 6;
                int rr_ = q >> 2, hh_ = q & 3;
                int corig = (hh_ * 4 + rr_) * 64 + (c2 & 63);
                sv[nt][qc] = sv_src[corig];
                tv[nt][qc] = sv_trg[corig];
            }
        int p_idx = wn >> 1;
#pragma unroll
        for (int mt = 0; mt < 4; mt++) {
            float s0 = 0.f, s1 = 0.f, t0 = 0.f, t1 = 0.f;
#pragma unroll
            for (int nt = 0; nt < 4; nt++)
#pragma unroll
                for (int qc = 0; qc < 2; qc++) {
                    s0 = fmaf(acc[mt][nt][qc],     sv[nt][qc], s0);
                    t0 = fmaf(acc[mt][nt][qc],     tv[nt][qc], t0);
                    s1 = fmaf(acc[mt][nt][2 + qc], sv[nt][qc], s1);
                    t1 = fmaf(acc[mt][nt][2 + qc], tv[nt][qc], t1);
                }
#pragma unroll
            for (int off = 1; off < 4; off <<= 1) {
                s0 += __shfl_xor_sync(0xffffffffu, s0, off);
                t0 += __shfl_xor_sync(0xffffffffu, t0, off);
                s1 += __shfl_xor_sync(0xffffffffu, s1, off);
                t1 += __shfl_xor_sync(0xffffffffu, t1, off);
            }
            if (tg == 0) {
                int r0 = wm * 64 + mt * 16 + g;
                atomicAdd(&sred[r0 * 4 + p_idx],           s0);
                atomicAdd(&sred[r0 * 4 + 2 + p_idx],       t0);
                atomicAdd(&sred[(r0 + 8) * 4 + p_idx],     s1);
                atomicAdd(&sred[(r0 + 8) * 4 + 2 + p_idx], t1);
            }
        }
        __syncthreads();
        int p0s = col0 >> 6;   // permuted slice base (q index)
        for (int i = t; i < 512; i += 256) {
            int row = i >> 2, j = i & 3;
            int n = row0 + row;
            if (n < NN) {
                float vval = sred[i];
                int p = p0s + (j & 1);
                if (j < 2) g_ssrc[n * 16 + p] = vval;
                else       g_strg[n * 16 + p] = vval;
            }
        }
    }
}

// ---------------- edge pass 1: per-(rel,head) max (q = r*4+h) ----------------
__global__ void __launch_bounds__(256) edge1_kernel(const int* __restrict__ src,
                                                    const int* __restrict__ trg,
                                                    const int* __restrict__ rel) {
    __shared__ unsigned sm[16];
    int t = threadIdx.x;
    if (t < 16) sm[t] = 0u;
    __syncthreads();
    int e = blockIdx.x * 256 + t;
    if (e < NE) {
        int r = rel[e];
        float4 a = *reinterpret_cast<const float4*>(g_ssrc + (size_t)src[e] * 16 + r * 4);
        float4 b = *reinterpret_cast<const float4*>(g_strg + (size_t)trg[e] * 16 + r * 4);
        float vv[4] = {a.x + b.x, a.y + b.y, a.z + b.z, a.w + b.w};
#pragma unroll
        for (int h = 0; h < 4; h++) {
            float v = (vv[h] > 0.f) ? vv[h] : 0.2f * vv[h];
            atomicMax(&sm[r * 4 + h], fenc(v));
        }
    }
    __syncthreads();
    if (t < 16 && sm[t] != 0u) atomicMax(&g_m_u[t], sm[t]);
}

// ---------------- counting sort: hist / scan x3 / scatter ----------------
__global__ void hist_kernel(const int* __restrict__ trg, const int* __restrict__ rel) {
    int e = blockIdx.x * 256 + threadIdx.x;
    if (e < NE) atomicAdd(&g_cnt[trg[e] * 4 + rel[e]], 1);
}

__global__ void __launch_bounds__(1024) scan1_kernel() {
    __shared__ int sd[1024];
    int t = threadIdx.x;
    int i = blockIdx.x * 1024 + t;
    int v = (i < NSEG) ? g_cnt[i] : 0;
    sd[t] = v;
    __syncthreads();
#pragma unroll
    for (int off = 1; off < 1024; off <<= 1) {
        int u = (t >= off) ? sd[t - off] : 0;
        __syncthreads();
        sd[t] += u;
        __syncthreads();
    }
    if (i < NSEG) g_off[i] = sd[t] - v;
    if (t == 1023) g_bsum[blockIdx.x] = sd[t];
}

__global__ void __launch_bounds__(256) scan2_kernel() {
    __shared__ int sd[256];
    int t = threadIdx.x;
    int v = (t < NB1) ? g_bsum[t] : 0;
    sd[t] = v;
    __syncthreads();
#pragma unroll
    for (int off = 1; off < 256; off <<= 1) {
        int u = (t >= off) ? sd[t - off] : 0;
        __syncthreads();
        sd[t] += u;
        __syncthreads();
    }
    if (t < NB1) g_bsum[t] = sd[t] - v;
    if (t == 0) g_off[NSEG] = NE;
}

__global__ void __launch_bounds__(1024) scan3_kernel() {
    int i = blockIdx.x * 1024 + threadIdx.x;
    if (i < NSEG) {
        int o = g_off[i] + g_bsum[blockIdx.x];
        g_off[i] = o;
        g_cur[i] = o;
    }
}

__global__ void scatter_kernel(const int* __restrict__ src, const int* __restrict__ trg,
                               const int* __restrict__ rel) {
    int e = blockIdx.x * 256 + threadIdx.x;
    if (e >= NE) return;
    int seg = trg[e] * 4 + rel[e];
    int pos = atomicAdd(&g_cur[seg], 1);
    g_psrc[pos] = src[e];
}

// ---------------- segment aggregation: contiguous 1KB gathers, packed bf16 out ------------
__global__ void __launch_bounds__(256) edge_agg_kernel() {
    int gw = (blockIdx.x * blockDim.x + threadIdx.x) >> 5;
    int lane = threadIdx.x & 31;
    if (gw >= NSEG) return;
    int seg = gw;
    int tg = seg >> 2, r = seg & 3;
    int beg = g_off[seg], end = g_off[seg + 1];

    float4 st4 = *reinterpret_cast<const float4*>(g_strg + (size_t)tg * 16 + r * 4);
    float strg_h[4] = {st4.x, st4.y, st4.z, st4.w};
    float m_h[4];
#pragma unroll
    for (int h = 0; h < 4; h++) m_h[h] = fdec(g_m_u[r * 4 + h]);

    float num0[4] = {0.f, 0.f, 0.f, 0.f};
    float num1[4] = {0.f, 0.f, 0.f, 0.f};
    float den[4]  = {0.f, 0.f, 0.f, 0.f};

    for (int i = beg; i < end; i++) {
        int s = g_psrc[i];
        const float* pb = g_ps + (size_t)s * CTOT + r * 256;   // contiguous [h][64]
        float4 sp4 = *reinterpret_cast<const float4*>(g_ssrc + (size_t)s * 16 + r * 4);
        float sv[4] = {sp4.x, sp4.y, sp4.z, sp4.w};
#pragma unroll
        for (int h = 0; h < 4; h++) {
            float v = sv[h] + strg_h[h];
            v = (v > 0.f) ? v : 0.2f * v;
            float ex = expf(v - m_h[h]);
            den[h] += ex;
            const float* pp = pb + h * 64;
            num0[h] = fmaf(ex, pp[lane],      num0[h]);
            num1[h] = fmaf(ex, pp[lane + 32], num1[h]);
        }
    }
#pragma unroll
    for (int h = 0; h < 4; h++) {
        float inv = 1.f / (den[h] + 1e-16f);
        unsigned* ag = g_aggp + ((size_t)seg * 4 + h) * 64;
        __nv_bfloat16 hi, lo;
        bsplit(num0[h] * inv, hi, lo); ag[lane]      = bpack(hi, lo);
        bsplit(num1[h] * inv, hi, lo); ag[lane + 32] = bpack(hi, lo);
    }
}

// ---------------- fused node kernel with tensor-core MLP ----------------
#define NS 200
#define NODE2_SMEM (128*NS*2*2 + 64*NS*2*2 + (64+64+64+128+128+32)*4)

__device__ __forceinline__ void mlp_layer(const __nv_bfloat16* __restrict__ Ain,
                                          const __nv_bfloat16* __restrict__ Wm,
                                          const float* __restrict__ bs,
                                          __nv_bfloat16* __restrict__ Hout, int t) {
    int lane = t & 31, w = t >> 5;
    int wm = w >> 2, wn = w & 3;
    int g = lane >> 2, tg = lane & 3;
    float acc[4][2][4];
#pragma unroll
    for (int i = 0; i < 4; i++)
#pragma unroll
        for (int j = 0; j < 2; j++)
#pragma unroll
            for (int q = 0; q < 4; q++) acc[i][j][q] = 0.f;

#pragma unroll
    for (int ks = 0; ks < 12; ks++) {
        int kk = ks * 16;
        unsigned af[4][4], bf_[2][2];
#pragma unroll
        for (int mt = 0; mt < 4; mt++) {
            const __nv_bfloat16* ap = Ain + (wm * 64 + mt * 16 + g) * NS + kk + tg * 2;
            af[mt][0] = *reinterpret_cast<const unsigned*>(ap);
            af[mt][1] = *reinterpret_cast<const unsigned*>(ap + 8 * NS);
            af[mt][2] = *reinterpret_cast<const unsigned*>(ap + 8);
            af[mt][3] = *reinterpret_cast<const unsigned*>(ap + 8 * NS + 8);
        }
#pragma unroll
        for (int nt = 0; nt < 2; nt++) {
            const __nv_bfloat16* bp = Wm + (wn * 16 + nt * 8 + g) * NS + kk + tg * 2;
            bf_[nt][0] = *reinterpret_cast<const unsigned*>(bp);
            bf_[nt][1] = *reinterpret_cast<const unsigned*>(bp + 8);
        }
#pragma unroll
        for (int mt = 0; mt < 4; mt++)
#pragma unroll
            for (int nt = 0; nt < 2; nt++)
                mma_bf16(acc[mt][nt], af[mt][0], af[mt][1], af[mt][2], af[mt][3],
                         bf_[nt][0], bf_[nt][1]);
    }
    __syncthreads();
#pragma unroll
    for (int mt = 0; mt < 4; mt++)
#pragma unroll
        for (int nt = 0; nt < 2; nt++) {
            int row = wm * 64 + mt * 16 + g;
            int col = wn * 16 + nt * 8 + tg * 2;
#pragma unroll
            for (int q = 0; q < 4; q++) {
                int rr = row + ((q >> 1) ? 8 : 0);
                int cc = col + (q & 1);
                float h = fmaxf(acc[mt][nt][q] + bs[cc], 0.f);
                __nv_bfloat16 hi, lo; bsplit(h, hi, lo);
                Hout[rr * NS + cc] = hi;
                Hout[rr * NS + 64 + cc] = lo;
                Hout[rr * NS + 128 + cc] = hi;
            }
        }
    __syncthreads();
}

__global__ void __launch_bounds__(256) node2_kernel(
        const float* __restrict__ b1, const float* __restrict__ b2,
        const float* __restrict__ W3, const float* __restrict__ b3,
        const float* __restrict__ bias, const float* __restrict__ gamma,
        const float* __restrict__ beta, float* __restrict__ out) {
    extern __shared__ char nsm[];
    __nv_bfloat16* Asp = reinterpret_cast<__nv_bfloat16*>(nsm);
    __nv_bfloat16* Hsp = Asp + 128 * NS;
    __nv_bfloat16* W1s = Hsp + 128 * NS;
    __nv_bfloat16* W2s = W1s + 64 * NS;
    float* W3s  = reinterpret_cast<float*>(W2s + 64 * NS);
    float* b1s  = W3s + 64;
    float* b2s  = b1s + 64;
    float* scs  = b2s + 64;
    float* alps = scs + 128;
    float* red  = alps + 128;

    int t = threadIdx.x;
    int node0 = blockIdx.x * 8;

    // load pre-split weights via uint4 (row stride NS=200 halves = 400B, 16B-aligned)
    for (int idx = t; idx < 3072; idx += 256) {
        int which = idx >= 1536;
        int rem = which ? idx - 1536 : idx;
        int n_ = rem / 24, c8 = rem % 24;
        uint4 v = reinterpret_cast<const uint4*>(g_w12)[idx];
        __nv_bfloat16* dst = (which ? W2s : W1s) + n_ * NS + c8 * 8;
        *reinterpret_cast<uint4*>(dst) = v;
    }
    if (t < 64) { W3s[t] = W3[t]; b1s[t] = b1[t]; b2s[t] = b2[t]; }

    // load packed agg; Asp row = ln*16 + h*4 + r, layout [hi | lo | hi]
    for (int idx = t; idx < 8192; idx += 256) {
        int row = idx >> 6, f = idx & 63;
        int ln = row >> 4, p = row & 15, h = p >> 2, r = p & 3;
        int n = node0 + ln;
        unsigned u = g_aggp[(((size_t)n * 4 + r) * 4 + h) * 64 + f];
        __nv_bfloat16 hi = __ushort_as_bfloat16((unsigned short)(u & 0xffffu));
        __nv_bfloat16 lo = __ushort_as_bfloat16((unsigned short)(u >> 16));
        Asp[row * NS + f] = hi; Asp[row * NS + 64 + f] = lo; Asp[row * NS + 128 + f] = hi;
    }
    __syncthreads();

    mlp_layer(Asp, W1s, b1s, Hsp, t);
    mlp_layer(Hsp, W2s, b2s, Hsp, t);

    if (t < 128) {
        float sacc = b3[0];
        const __nv_bfloat16* hp = Hsp + t * NS;
#pragma unroll
        for (int j = 0; j < 64; j++) {
            float hv = __bfloat162float(hp[j]) + __bfloat162float(hp[64 + j]);
            sacc = fmaf(hv, W3s[j], sacc);
        }
        float sp = (sacc > 20.f) ? sacc : log1pf(expf(sacc));
        scs[t] = sacc * tanhf(sp);
    }
    __syncthreads();

    if (t < 32) {
        int base = (t >> 2) * 16 + (t & 3) * 4;
        float mx = -1e30f;
#pragma unroll
        for (int r = 0; r < 4; r++) mx = fmaxf(mx, scs[base + r]);
        float ev[4], ssum = 0.f;
#pragma unroll
        for (int r = 0; r < 4; r++) { ev[r] = expf(scs[base + r] - mx); ssum += ev[r]; }
#pragma unroll
        for (int r = 0; r < 4; r++) alps[base + r] = ev[r] / ssum;
    }
    __syncthreads();

    int hh = t >> 6, f = t & 63;
    int wid = t >> 5, lane = t & 31;
#pragma unroll 1
    for (int s = 0; s < 8; s++) {
        int n = node0 + s;
        int rb = s * 16 + hh * 4;
        float o = 0.f;
#pragma unroll
        for (int r = 0; r < 4; r++) {
            const __nv_bfloat16* ap = Asp + (rb + r) * NS;
            float a = __bfloat162float(ap[f]) + __bfloat162float(ap[64 + f]);
            o = fmaf(a, alps[rb + r], o);
        }
        o += g_ps[(size_t)n * CTOT + CPROJ + t];
        o += bias[t];
        o = (o > 0.f) ? o : expm1f(o);

        float s1 = o, s2 = o * o;
#pragma unroll
        for (int off = 16; off > 0; off >>= 1) {
            s1 += __shfl_down_sync(0xffffffffu, s1, off);
            s2 += __shfl_down_sync(0xffffffffu, s2, off);
        }
        if (lane == 0) { red[wid] = s1; red[8 + wid] = s2; }
        __syncthreads();
        if (t == 0) {
            float S1 = 0.f, S2 = 0.f;
#pragma unroll
            for (int w = 0; w < 8; w++) { S1 += red[w]; S2 += red[8 + w]; }
            float mu = S1 * (1.f / 256.f);
            float var = S2 * (1.f / 256.f) - mu * mu;
            red[16] = mu;
            red[17] = rsqrtf(var + 1e-5f);
        }
        __syncthreads();
        float mu = red[16], rstd = red[17];
        out[(size_t)n * 256 + t] = (o - mu) * rstd * gamma[t] + beta[t];
        __syncthreads();
    }
}

// ---------------- launch ----------------
extern "C" void kernel_launch(void* const* d_in, const int* in_sizes, int n_in,
                              void* d_out, int out_size) {
    const float* x         = (const float*)d_in[0];
    const int*   src       = (const int*)d_in[1];
    const int*   trg       = (const int*)d_in[2];
    const int*   rel       = (const int*)d_in[3];
    // d_in[4] = node_to_graph_map (unused)
    const float* W_proj    = (const float*)d_in[5];
    const float* score_src = (const float*)d_in[6];
    const float* score_trg = (const float*)d_in[7];
    const float* W1        = (const float*)d_in[8];
    const float* b1        = (const float*)d_in[9];
    const float* W2        = (const float*)d_in[10];
    const float* b2        = (const float*)d_in[11];
    const float* W3        = (const float*)d_in[12];
    const float* b3        = (const float*)d_in[13];
    const float* W_skip    = (const float*)d_in[14];
    const float* bias      = (const float*)d_in[15];
    const float* gamma     = (const float*)d_in[16];
    const float* beta      = (const float*)d_in[17];
    float* out = (float*)d_out;

    cudaFuncSetAttribute(node2_kernel, cudaFuncAttributeMaxDynamicSharedMemorySize, NODE2_SMEM);
    cudaFuncSetAttribute(gemm_bf16_kernel, cudaFuncAttributeMaxDynamicSharedMemorySize, GSMEM);

    prep_wext_kernel<<<(CTOT * FIN + 511) / 512, 512>>>(W_proj, W_skip);
    prep_aext_kernel<<<8192, 256>>>(x);
    prep_w12_kernel<<<(2 * 64 * 64 + 255) / 256, 256>>>(W1, W2);
    zero_kernel<<<784, 256>>>();

    dim3 ggrid(CTOT / 128, (NN + 127) / 128);
    gemm_bf16_kernel<<<ggrid, 256, GSMEM>>>(score_src, score_trg);

    int eb = (NE + 255) / 256;
    edge1_kernel<<<eb, 256>>>(src, trg, rel);

    // counting sort by (trg, rel)
    hist_kernel<<<eb, 256>>>(trg, rel);
    scan1_kernel<<<NB1, 1024>>>();
    scan2_kernel<<<1, 256>>>();
    scan3_kernel<<<NB1, 1024>>>();
    scatter_kernel<<<eb, 256>>>(src, trg, rel);

    // atomic-free aggregation
    edge_agg_kernel<<<(NSEG * 32 + 255) / 256, 256>>>();

    node2_kernel<<<NN / 8, 256, NODE2_SMEM>>>(b1, b2, W3, b3, bias, gamma, beta, out);
}

// round 15
// speedup vs baseline: 1.4411x; 1.3135x over previous
#include <cuda_runtime.h>
#include <cuda_bf16.h>
#include <math.h>

// Problem constants
#define NN     50000
#define FIN    256
#define NH     4
#define NR     4
#define FF     64
#define NE     500000
#define CPROJ  1024          // NH*NR*FF
#define CTOT   1280          // CPROJ + NH*FF (skip)
#define NSEG   (NN * NR)     // 200000 (trg, rel) segments
#define NB1    ((NSEG + 1023) / 1024)   // 196 scan blocks

// ---------------- scratch (device globals; no allocation allowed) ----------------
// proj layout PERMUTED: col = r*256 + h*64 + f   (skip still at cols 1024..1279, h*64+f)
__device__ float         g_ps[(size_t)NN * CTOT];
__device__ unsigned      g_aggp[(size_t)NSEG * NH * FF];   // packed bf16 (hi lo) per value
__device__ float         g_ssrc[(size_t)NN * NH * NR];     // [n*16 + r*4 + h]
__device__ float         g_strg[(size_t)NN * NH * NR];
__device__ unsigned      g_m_u[NR * NH];                   // index q = r*4 + h
__device__ __align__(16) __nv_bfloat16 g_aext[(size_t)NN * 512];   // [n][512] = [x_hi | x_lo]
__device__ __align__(16) __nv_bfloat16 g_bext[(size_t)CTOT * 512]; // [c'][512] = [W_hi | W_lo]
__device__ __align__(16) __nv_bfloat16 g_w12[2 * 64 * 128];        // pre-split W1/W2 [hi(64)|lo(64)]
// edge sort scratch
__device__ int           g_cnt[NSEG];
__device__ int           g_off[NSEG + 1];
__device__ int           g_cur[NSEG];
__device__ int           g_bsum[256];
__device__ int           g_psrc[NE];                       // src[], permuted by segment

// ---------------- helpers ----------------
__device__ __forceinline__ unsigned fenc(float f) {
    unsigned u = __float_as_uint(f);
    return (u & 0x80000000u) ? ~u : (u | 0x80000000u);
}
__device__ __forceinline__ float fdec(unsigned u) {
    return (u & 0x80000000u) ? __uint_as_float(u & 0x7fffffffu) : __uint_as_float(~u);
}
__device__ __forceinline__ void bsplit(float w, __nv_bfloat16& hi, __nv_bfloat16& lo) {
    hi = __float2bfloat16(w);
    lo = __float2bfloat16(w - __bfloat162float(hi));
}
__device__ __forceinline__ unsigned bpack(__nv_bfloat16 h, __nv_bfloat16 l) {
    return ((unsigned)__bfloat16_as_ushort(l) << 16) | (unsigned)__bfloat16_as_ushort(h);
}
__device__ __forceinline__ void mma_bf16(float* c, unsigned a0, unsigned a1, unsigned a2,
                                         unsigned a3, unsigned b0, unsigned b1) {
    asm volatile(
        "mma.sync.aligned.m16n8k16.row.col.f32.bf16.bf16.f32 "
        "{%0,%1,%2,%3}, {%4,%5,%6,%7}, {%8,%9}, {%0,%1,%2,%3};\n"
        : "+f"(c[0]), "+f"(c[1]), "+f"(c[2]), "+f"(c[3])
        : "r"(a0), "r"(a1), "r"(a2), "r"(a3), "r"(b0), "r"(b1));
}
__device__ __forceinline__ void ldsm4(unsigned& r0, unsigned& r1, unsigned& r2, unsigned& r3,
                                      const void* p) {
    unsigned addr = (unsigned)__cvta_generic_to_shared(p);
    asm volatile("ldmatrix.sync.aligned.m8n8.x4.shared.b16 {%0,%1,%2,%3}, [%4];\n"
                 : "=r"(r0), "=r"(r1), "=r"(r2), "=r"(r3) : "r"(addr));
}
__device__ __forceinline__ void cp16(void* smem, const void* g, bool pred) {
    unsigned s = (unsigned)__cvta_generic_to_shared(smem);
    int sz = pred ? 16 : 0;
    asm volatile("cp.async.cg.shared.global [%0], [%1], 16, %2;\n" :: "r"(s), "l"(g), "r"(sz));
}
template <int N> __device__ __forceinline__ void cpwait() {
    asm volatile("cp.async.wait_group %0;\n" :: "n"(N) : "memory");
}

// ---------------- prep kernels ----------------
__global__ void prep_wext_kernel(const float* __restrict__ Wp, const float* __restrict__ Ws) {
    int idx = blockIdx.x * blockDim.x + threadIdx.x;
    if (idx >= CTOT * FIN) return;
    int c = idx >> 8, k = idx & 255;
    float w; int c2;
    if (c < CPROJ) {
        w = Wp[idx];
        int h = c >> 8, r = (c >> 6) & 3, f = c & 63;
        c2 = r * 256 + h * 64 + f;          // permuted: [r][h][f]
    } else {
        w = Ws[(c - CPROJ) * FIN + k];
        c2 = c;
    }
    __nv_bfloat16 hi, lo; bsplit(w, hi, lo);
    size_t b = (size_t)c2 * 512;
    g_bext[b + k] = hi; g_bext[b + 256 + k] = lo;
}

__global__ void prep_aext_kernel(const float* __restrict__ x) {
    int idx = blockIdx.x * blockDim.x + threadIdx.x;
    int tot = NN * FIN;
    for (; idx < tot; idx += gridDim.x * blockDim.x) {
        int n = idx >> 8, k = idx & 255;
        float w = x[idx];
        __nv_bfloat16 hi, lo; bsplit(w, hi, lo);
        size_t b = (size_t)n * 512;
        g_aext[b + k] = hi; g_aext[b + 256 + k] = lo;
    }
}

// pre-split node MLP weights into [hi(64) | lo(64)] rows of 128
__global__ void prep_w12_kernel(const float* __restrict__ W1, const float* __restrict__ W2) {
    int idx = blockIdx.x * blockDim.x + threadIdx.x;
    if (idx >= 2 * 64 * 64) return;
    int which = idx >> 12, rem = idx & 4095;
    int n_ = rem >> 6, k_ = rem & 63;
    float w = which ? W2[rem] : W1[rem];
    __nv_bfloat16 hi, lo; bsplit(w, hi, lo);
    int base = which * 64 * 128 + n_ * 128;
    g_w12[base + k_] = hi; g_w12[base + 64 + k_] = lo;
}

// ---------------- zero small scratch ----------------
__global__ void zero_kernel() {
    int idx = blockIdx.x * blockDim.x + threadIdx.x;
    for (int i = idx; i < NSEG; i += gridDim.x * blockDim.x) g_cnt[i] = 0;
    if (idx < NR * NH) g_m_u[idx] = 0u;
}

// ---------------- K2: bf16 TC GEMM — cp.async 2-stage, ldmatrix, fused scores ----------
#define GSTR  40                        // smem row stride in halves (80B)
#define TILEH (128 * GSTR)              // halves per 128x32 tile
#define TILEB (TILEH * 2)               // 10240 bytes
#define GSMEM (8 * TILEB + 512 * 4)     // 2 stages x 4 tiles + sred = 83968

__global__ void __launch_bounds__(256) gemm_bf16_kernel(const float* __restrict__ sv_src,
                                                        const float* __restrict__ sv_trg) {
    extern __shared__ char gsm[];
    __nv_bfloat16* A0h = reinterpret_cast<__nv_bfloat16*>(gsm);
    __nv_bfloat16* A0l = A0h + TILEH;
    __nv_bfloat16* B0h = A0l + TILEH;
    __nv_bfloat16* B0l = B0h + TILEH;
    __nv_bfloat16* A1h = B0l + TILEH;
    __nv_bfloat16* A1l = A1h + TILEH;
    __nv_bfloat16* B1h = A1l + TILEH;
    __nv_bfloat16* B1l = B1h + TILEH;
    float* sred = reinterpret_cast<float*>(gsm + 8 * TILEB);

    int t = threadIdx.x;
    int lane = t & 31, w = t >> 5;
    int wm = w >> 2, wn = w & 3;           // wm 0..1 (64 rows), wn 0..3 (32 cols)
    int g = lane >> 2, tg = lane & 3;
    int row0 = blockIdx.y * 128;
    int col0 = blockIdx.x * 128;

    float acc[4][4][4];
#pragma unroll
    for (int i = 0; i < 4; i++)
#pragma unroll
        for (int j = 0; j < 4; j++)
#pragma unroll
            for (int q = 0; q < 4; q++) acc[i][j][q] = 0.f;

    int r0v = t >> 2;                 // 0..63
    int kcv = (t & 3) * 8;            // 0,8,16,24
    int fr = lane & 15;
    int fcb = (lane >> 4) * 8;

    int ga0 = row0 + r0v, ga1 = row0 + r0v + 64;
    bool p0 = ga0 < NN, p1 = ga1 < NN;
    const __nv_bfloat16* apA0 = g_aext + (size_t)(p0 ? ga0 : 0) * 512 + kcv;
    const __nv_bfloat16* apA1 = g_aext + (size_t)(p1 ? ga1 : 0) * 512 + kcv;
    const __nv_bfloat16* bpB0 = g_bext + (size_t)(col0 + r0v) * 512 + kcv;
    const __nv_bfloat16* bpB1 = g_bext + (size_t)(col0 + r0v + 64) * 512 + kcv;
    int d0 = r0v * GSTR + kcv;
    int d1 = (r0v + 64) * GSTR + kcv;

    auto issue = [&](int c, __nv_bfloat16* Ah, __nv_bfloat16* Al,
                     __nv_bfloat16* Bh, __nv_bfloat16* Bl) {
        int k0 = c * 32;
        cp16(Ah + d0, apA0 + k0,       p0);
        cp16(Al + d0, apA0 + 256 + k0, p0);
        cp16(Ah + d1, apA1 + k0,       p1);
        cp16(Al + d1, apA1 + 256 + k0, p1);
        cp16(Bh + d0, bpB0 + k0,       true);
        cp16(Bl + d0, bpB0 + 256 + k0, true);
        cp16(Bh + d1, bpB1 + k0,       true);
        cp16(Bl + d1, bpB1 + 256 + k0, true);
        asm volatile("cp.async.commit_group;\n" ::: "memory");
    };

    auto compute = [&](const __nv_bfloat16* Ah, const __nv_bfloat16* Al,
                       const __nv_bfloat16* Bh, const __nv_bfloat16* Bl) {
#pragma unroll
        for (int kk = 0; kk < 32; kk += 16) {
            int fc = kk + fcb;
            unsigned bhf[2][4], blf[2][4];
#pragma unroll
            for (int np = 0; np < 2; np++) {
                int n = wn * 32 + np * 16 + fr;
                ldsm4(bhf[np][0], bhf[np][1], bhf[np][2], bhf[np][3], Bh + n * GSTR + fc);
                ldsm4(blf[np][0], blf[np][1], blf[np][2], blf[np][3], Bl + n * GSTR + fc);
            }
#pragma unroll
            for (int mt = 0; mt < 4; mt++) {
                int r = wm * 64 + mt * 16 + fr;
                unsigned a0, a1, a2, a3;
                ldsm4(a0, a1, a2, a3, Ah + r * GSTR + fc);
#pragma unroll
                for (int nt = 0; nt < 4; nt++) {
                    int np = nt >> 1, sel = nt & 1;
                    mma_bf16(acc[mt][nt], a0, a1, a2, a3, bhf[np][sel], bhf[np][sel + 2]);
                    mma_bf16(acc[mt][nt], a0, a1, a2, a3, blf[np][sel], blf[np][sel + 2]);
                }
            }
#pragma unroll
            for (int mt = 0; mt < 4; mt++) {
                int r = wm * 64 + mt * 16 + fr;
                unsigned a0, a1, a2, a3;
                ldsm4(a0, a1, a2, a3, Al + r * GSTR + fc);
#pragma unroll
                for (int nt = 0; nt < 4; nt++) {
                    int np = nt >> 1, sel = nt & 1;
                    mma_bf16(acc[mt][nt], a0, a1, a2, a3, bhf[np][sel], bhf[np][sel + 2]);
                }
            }
        }
    };

    issue(0, A0h, A0l, B0h, B0l);
    issue(1, A1h, A1l, B1h, B1l);

#pragma unroll
    for (int c = 0; c < 8; c++) {
        if (c < 7) cpwait<1>(); else cpwait<0>();
        __syncthreads();
        if ((c & 1) == 0) {
            compute(A0h, A0l, B0h, B0l);
            __syncthreads();
            if (c + 2 < 8) issue(c + 2, A0h, A0l, B0h, B0l);
        } else {
            compute(A1h, A1l, B1h, B1l);
            __syncthreads();
            if (c + 2 < 8) issue(c + 2, A1h, A1l, B1h, B1l);
        }
    }

    // write proj/skip
#pragma unroll
    for (int mt = 0; mt < 4; mt++)
#pragma unroll
        for (int nt = 0; nt < 4; nt++) {
            int row = row0 + wm * 64 + mt * 16 + g;
            int col = col0 + wn * 32 + nt * 8 + tg * 2;
            if (row < NN) {
                float2 o = make_float2(acc[mt][nt][0], acc[mt][nt][1]);
                *reinterpret_cast<float2*>(g_ps + (size_t)row * CTOT + col) = o;
            }
            if (row + 8 < NN) {
                float2 o = make_float2(acc[mt][nt][2], acc[mt][nt][3]);
                *reinterpret_cast<float2*>(g_ps + (size_t)(row + 8) * CTOT + col) = o;
            }
        }

    // fused attention-score epilogue (proj columns only; permuted slice q = r*4+h)
    if (col0 < CPROJ) {
        __syncthreads();
        for (int i = t; i < 512; i += 256) sred[i] = 0.f;
        __syncthreads();

        float sv[4][2], tv[4][2];
#pragma unroll
        for (int nt = 0; nt < 4; nt++)
#pragma unroll
            for (int qc = 0; qc < 2; qc++) {
                int c2 = col0 + wn * 32 + nt * 8 + tg * 2 + qc;
                int q = c2 >> 6;
                int rr_ = q >> 2, hh_ = q & 3;
                int corig = (hh_ * 4 + rr_) * 64 + (c2 & 63);
                sv[nt][qc] = sv_src[corig];
                tv[nt][qc] = sv_trg[corig];
            }
        int p_idx = wn >> 1;
#pragma unroll
        for (int mt = 0; mt < 4; mt++) {
            float s0 = 0.f, s1 = 0.f, t0 = 0.f, t1 = 0.f;
#pragma unroll
            for (int nt = 0; nt < 4; nt++)
#pragma unroll
                for (int qc = 0; qc < 2; qc++) {
                    s0 = fmaf(acc[mt][nt][qc],     sv[nt][qc], s0);
                    t0 = fmaf(acc[mt][nt][qc],     tv[nt][qc], t0);
                    s1 = fmaf(acc[mt][nt][2 + qc], sv[nt][qc], s1);
                    t1 = fmaf(acc[mt][nt][2 + qc], tv[nt][qc], t1);
                }
#pragma unroll
            for (int off = 1; off < 4; off <<= 1) {
                s0 += __shfl_xor_sync(0xffffffffu, s0, off);
                t0 += __shfl_xor_sync(0xffffffffu, t0, off);
                s1 += __shfl_xor_sync(0xffffffffu, s1, off);
                t1 += __shfl_xor_sync(0xffffffffu, t1, off);
            }
            if (tg == 0) {
                int r0 = wm * 64 + mt * 16 + g;
                atomicAdd(&sred[r0 * 4 + p_idx],           s0);
                atomicAdd(&sred[r0 * 4 + 2 + p_idx],       t0);
                atomicAdd(&sred[(r0 + 8) * 4 + p_idx],     s1);
                atomicAdd(&sred[(r0 + 8) * 4 + 2 + p_idx], t1);
            }
        }
        __syncthreads();
        int p0s = col0 >> 6;
        for (int i = t; i < 512; i += 256) {
            int row = i >> 2, j = i & 3;
            int n = row0 + row;
            if (n < NN) {
                float vval = sred[i];
                int p = p0s + (j & 1);
                if (j < 2) g_ssrc[n * 16 + p] = vval;
                else       g_strg[n * 16 + p] = vval;
            }
        }
    }
}

// ---------------- edge pass 1: per-(rel,head) max (q = r*4+h) ----------------
__global__ void __launch_bounds__(256) edge1_kernel(const int* __restrict__ src,
                                                    const int* __restrict__ trg,
                                                    const int* __restrict__ rel) {
    __shared__ unsigned sm[16];
    int t = threadIdx.x;
    if (t < 16) sm[t] = 0u;
    __syncthreads();
    int e = blockIdx.x * 256 + t;
    if (e < NE) {
        int r = rel[e];
        float4 a = *reinterpret_cast<const float4*>(g_ssrc + (size_t)src[e] * 16 + r * 4);
        float4 b = *reinterpret_cast<const float4*>(g_strg + (size_t)trg[e] * 16 + r * 4);
        float vv[4] = {a.x + b.x, a.y + b.y, a.z + b.z, a.w + b.w};
#pragma unroll
        for (int h = 0; h < 4; h++) {
            float v = (vv[h] > 0.f) ? vv[h] : 0.2f * vv[h];
            atomicMax(&sm[r * 4 + h], fenc(v));
        }
    }
    __syncthreads();
    if (t < 16 && sm[t] != 0u) atomicMax(&g_m_u[t], sm[t]);
}

// ---------------- counting sort: hist / scan x3 / scatter ----------------
__global__ void hist_kernel(const int* __restrict__ trg, const int* __restrict__ rel) {
    int e = blockIdx.x * 256 + threadIdx.x;
    if (e < NE) atomicAdd(&g_cnt[trg[e] * 4 + rel[e]], 1);
}

__global__ void __launch_bounds__(1024) scan1_kernel() {
    __shared__ int sd[1024];
    int t = threadIdx.x;
    int i = blockIdx.x * 1024 + t;
    int v = (i < NSEG) ? g_cnt[i] : 0;
    sd[t] = v;
    __syncthreads();
#pragma unroll
    for (int off = 1; off < 1024; off <<= 1) {
        int u = (t >= off) ? sd[t - off] : 0;
        __syncthreads();
        sd[t] += u;
        __syncthreads();
    }
    if (i < NSEG) g_off[i] = sd[t] - v;
    if (t == 1023) g_bsum[blockIdx.x] = sd[t];
}

__global__ void __launch_bounds__(256) scan2_kernel() {
    __shared__ int sd[256];
    int t = threadIdx.x;
    int v = (t < NB1) ? g_bsum[t] : 0;
    sd[t] = v;
    __syncthreads();
#pragma unroll
    for (int off = 1; off < 256; off <<= 1) {
        int u = (t >= off) ? sd[t - off] : 0;
        __syncthreads();
        sd[t] += u;
        __syncthreads();
    }
    if (t < NB1) g_bsum[t] = sd[t] - v;
    if (t == 0) g_off[NSEG] = NE;
}

__global__ void __launch_bounds__(1024) scan3_kernel() {
    int i = blockIdx.x * 1024 + threadIdx.x;
    if (i < NSEG) {
        int o = g_off[i] + g_bsum[blockIdx.x];
        g_off[i] = o;
        g_cur[i] = o;
    }
}

__global__ void scatter_kernel(const int* __restrict__ src, const int* __restrict__ trg,
                               const int* __restrict__ rel) {
    int e = blockIdx.x * 256 + threadIdx.x;
    if (e >= NE) return;
    int seg = trg[e] * 4 + rel[e];
    int pos = atomicAdd(&g_cur[seg], 1);
    g_psrc[pos] = src[e];
}

// ---------------- segment aggregation: 2-edge pipelined gathers, packed bf16 out ----------
__global__ void __launch_bounds__(256) edge_agg_kernel() {
    int gw = (blockIdx.x * blockDim.x + threadIdx.x) >> 5;
    int lane = threadIdx.x & 31;
    if (gw >= NSEG) return;
    int seg = gw;
    int tg = seg >> 2, r = seg & 3;
    int beg = g_off[seg], end = g_off[seg + 1];

    float4 st4 = *reinterpret_cast<const float4*>(g_strg + (size_t)tg * 16 + r * 4);
    float strg_h[4] = {st4.x, st4.y, st4.z, st4.w};
    float m_h[4];
#pragma unroll
    for (int h = 0; h < 4; h++) m_h[h] = fdec(g_m_u[r * 4 + h]);

    float num0[4] = {0.f, 0.f, 0.f, 0.f};
    float num1[4] = {0.f, 0.f, 0.f, 0.f};
    float den[4]  = {0.f, 0.f, 0.f, 0.f};

    for (int i = beg; i < end; i += 2) {
        int sA = g_psrc[i];
        bool hb = (i + 1 < end);
        int sB = g_psrc[hb ? i + 1 : i];
        const float* pa = g_ps + (size_t)sA * CTOT + r * 256;
        const float* pb = g_ps + (size_t)sB * CTOT + r * 256;
        float4 spa = *reinterpret_cast<const float4*>(g_ssrc + (size_t)sA * 16 + r * 4);
        float4 spb = *reinterpret_cast<const float4*>(g_ssrc + (size_t)sB * 16 + r * 4);
        float svA[4] = {spa.x, spa.y, spa.z, spa.w};
        float svB[4] = {spb.x, spb.y, spb.z, spb.w};
        float gA0[4], gA1[4], gB0[4], gB1[4];
#pragma unroll
        for (int h = 0; h < 4; h++) {
            gA0[h] = pa[h * 64 + lane];
            gA1[h] = pa[h * 64 + lane + 32];
            gB0[h] = pb[h * 64 + lane];
            gB1[h] = pb[h * 64 + lane + 32];
        }
        float bm = hb ? 1.f : 0.f;
#pragma unroll
        for (int h = 0; h < 4; h++) {
            float vA = svA[h] + strg_h[h];
            vA = (vA > 0.f) ? vA : 0.2f * vA;
            float exA = expf(vA - m_h[h]);
            float vB = svB[h] + strg_h[h];
            vB = (vB > 0.f) ? vB : 0.2f * vB;
            float exB = expf(vB - m_h[h]) * bm;
            den[h] += exA + exB;
            num0[h] = fmaf(exA, gA0[h], num0[h]);
            num1[h] = fmaf(exA, gA1[h], num1[h]);
            num0[h] = fmaf(exB, gB0[h], num0[h]);
            num1[h] = fmaf(exB, gB1[h], num1[h]);
        }
    }
#pragma unroll
    for (int h = 0; h < 4; h++) {
        float inv = 1.f / (den[h] + 1e-16f);
        unsigned* ag = g_aggp + ((size_t)seg * 4 + h) * 64;
        __nv_bfloat16 hi, lo;
        bsplit(num0[h] * inv, hi, lo); ag[lane]      = bpack(hi, lo);
        bsplit(num1[h] * inv, hi, lo); ag[lane + 32] = bpack(hi, lo);
    }
}

// ---------------- fused node kernel with tensor-core MLP (compact [hi|lo] layout) --------
#define NS2 136   // smem row stride in halves (272B) — conflict-free ldmatrix
#define NODE2_SMEM ((128 + 128 + 64 + 64) * NS2 * 2 + (64*3 + 128*2 + 32) * 4)

// 3-pass split mma over [hi(64)|lo(64)] tiles: A_hi*W_hi + A_lo*W_hi + A_hi*W_lo
__device__ __forceinline__ void mlp_layer(const __nv_bfloat16* __restrict__ Ain,
                                          const __nv_bfloat16* __restrict__ Wm,
                                          const float* __restrict__ bs,
                                          __nv_bfloat16* __restrict__ Hout, int t) {
    int lane = t & 31, w = t >> 5;
    int wm = w >> 2, wn = w & 3;
    int g = lane >> 2, tg = lane & 3;
    float acc[4][2][4];
#pragma unroll
    for (int i = 0; i < 4; i++)
#pragma unroll
        for (int j = 0; j < 2; j++)
#pragma unroll
            for (int q = 0; q < 4; q++) acc[i][j][q] = 0.f;

#pragma unroll
    for (int pass = 0; pass < 3; pass++) {
        int aoff = (pass == 1) ? 64 : 0;
        int woff = (pass == 2) ? 64 : 0;
#pragma unroll
        for (int ks = 0; ks < 4; ks++) {
            int kk = ks * 16;
            unsigned af[4][4], bf_[2][2];
#pragma unroll
            for (int mt = 0; mt < 4; mt++) {
                const __nv_bfloat16* ap = Ain + (wm * 64 + mt * 16 + g) * NS2 + aoff + kk + tg * 2;
                af[mt][0] = *reinterpret_cast<const unsigned*>(ap);
                af[mt][1] = *reinterpret_cast<const unsigned*>(ap + 8 * NS2);
                af[mt][2] = *reinterpret_cast<const unsigned*>(ap + 8);
                af[mt][3] = *reinterpret_cast<const unsigned*>(ap + 8 * NS2 + 8);
            }
#pragma unroll
            for (int nt = 0; nt < 2; nt++) {
                const __nv_bfloat16* bp = Wm + (wn * 16 + nt * 8 + g) * NS2 + woff + kk + tg * 2;
                bf_[nt][0] = *reinterpret_cast<const unsigned*>(bp);
                bf_[nt][1] = *reinterpret_cast<const unsigned*>(bp + 8);
            }
#pragma unroll
            for (int mt = 0; mt < 4; mt++)
#pragma unroll
                for (int nt = 0; nt < 2; nt++)
                    mma_bf16(acc[mt][nt], af[mt][0], af[mt][1], af[mt][2], af[mt][3],
                             bf_[nt][0], bf_[nt][1]);
        }
    }
    __syncthreads();
#pragma unroll
    for (int mt = 0; mt < 4; mt++)
#pragma unroll
        for (int nt = 0; nt < 2; nt++) {
            int row = wm * 64 + mt * 16 + g;
            int col = wn * 16 + nt * 8 + tg * 2;
#pragma unroll
            for (int q = 0; q < 4; q++) {
                int rr = row + ((q >> 1) ? 8 : 0);
                int cc = col + (q & 1);
                float h = fmaxf(acc[mt][nt][q] + bs[cc], 0.f);
                __nv_bfloat16 hi, lo; bsplit(h, hi, lo);
                Hout[rr * NS2 + cc] = hi;
                Hout[rr * NS2 + 64 + cc] = lo;
            }
        }
    __syncthreads();
}

__global__ void __launch_bounds__(256) node2_kernel(
        const float* __restrict__ b1, const float* __restrict__ b2,
        const float* __restrict__ W3, const float* __restrict__ b3,
        const float* __restrict__ bias, const float* __restrict__ gamma,
        const float* __restrict__ beta, float* __restrict__ out) {
    extern __shared__ char nsm[];
    __nv_bfloat16* Asp = reinterpret_cast<__nv_bfloat16*>(nsm);
    __nv_bfloat16* Hsp = Asp + 128 * NS2;
    __nv_bfloat16* W1s = Hsp + 128 * NS2;
    __nv_bfloat16* W2s = W1s + 64 * NS2;
    float* W3s  = reinterpret_cast<float*>(W2s + 64 * NS2);
    float* b1s  = W3s + 64;
    float* b2s  = b1s + 64;
    float* scs  = b2s + 64;
    float* alps = scs + 128;
    float* red  = alps + 128;

    int t = threadIdx.x;
    int node0 = blockIdx.x * 8;

    // load pre-split weights via uint4 (row stride NS2=136 halves = 272B, 16B-aligned)
    for (int idx = t; idx < 2048; idx += 256) {
        int which = idx >= 1024;
        int rem = which ? idx - 1024 : idx;
        int n_ = rem >> 4, c8 = rem & 15;
        uint4 v = reinterpret_cast<const uint4*>(g_w12)[idx];
        __nv_bfloat16* dst = (which ? W2s : W1s) + n_ * NS2 + c8 * 8;
        *reinterpret_cast<uint4*>(dst) = v;
    }
    if (t < 64) { W3s[t] = W3[t]; b1s[t] = b1[t]; b2s[t] = b2[t]; }

    // load packed agg; Asp row = ln*16 + h*4 + r, layout [hi | lo]
    for (int idx = t; idx < 8192; idx += 256) {
        int row = idx >> 6, f = idx & 63;
        int ln = row >> 4, p = row & 15, h = p >> 2, r = p & 3;
        int n = node0 + ln;
        unsigned u = g_aggp[(((size_t)n * 4 + r) * 4 + h) * 64 + f];
        __nv_bfloat16 hi = __ushort_as_bfloat16((unsigned short)(u & 0xffffu));
        __nv_bfloat16 lo = __ushort_as_bfloat16((unsigned short)(u >> 16));
        Asp[row * NS2 + f] = hi; Asp[row * NS2 + 64 + f] = lo;
    }
    __syncthreads();

    mlp_layer(Asp, W1s, b1s, Hsp, t);
    mlp_layer(Hsp, W2s, b2s, Hsp, t);

    if (t < 128) {
        float sacc = b3[0];
        const __nv_bfloat16* hp = Hsp + t * NS2;
#pragma unroll
        for (int j = 0; j < 64; j++) {
            float hv = __bfloat162float(hp[j]) + __bfloat162float(hp[64 + j]);
            sacc = fmaf(hv, W3s[j], sacc);
        }
        float sp = (sacc > 20.f) ? sacc : log1pf(expf(sacc));
        scs[t] = sacc * tanhf(sp);
    }
    __syncthreads();

    if (t < 32) {
        int base = (t >> 2) * 16 + (t & 3) * 4;
        float mx = -1e30f;
#pragma unroll
        for (int r = 0; r < 4; r++) mx = fmaxf(mx, scs[base + r]);
        float ev[4], ssum = 0.f;
#pragma unroll
        for (int r = 0; r < 4; r++) { ev[r] = expf(scs[base + r] - mx); ssum += ev[r]; }
#pragma unroll
        for (int r = 0; r < 4; r++) alps[base + r] = ev[r] / ssum;
    }
    __syncthreads();

    int hh = t >> 6, f = t & 63;
    int wid = t >> 5, lane = t & 31;
#pragma unroll 1
    for (int s = 0; s < 8; s++) {
        int n = node0 + s;
        int rb = s * 16 + hh * 4;
        float o = 0.f;
#pragma unroll
        for (int r = 0; r < 4; r++) {
            const __nv_bfloat16* ap = Asp + (rb + r) * NS2;
            float a = __bfloat162float(ap[f]) + __bfloat162float(ap[64 + f]);
            o = fmaf(a, alps[rb + r], o);
        }
        o += g_ps[(size_t)n * CTOT + CPROJ + t];
        o += bias[t];
        o = (o > 0.f) ? o : expm1f(o);

        float s1 = o, s2 = o * o;
#pragma unroll
        for (int off = 16; off > 0; off >>= 1) {
            s1 += __shfl_down_sync(0xffffffffu, s1, off);
            s2 += __shfl_down_sync(0xffffffffu, s2, off);
        }
        if (lane == 0) { red[wid] = s1; red[8 + wid] = s2; }
        __syncthreads();
        if (t == 0) {
            float S1 = 0.f, S2 = 0.f;
#pragma unroll
            for (int w = 0; w < 8; w++) { S1 += red[w]; S2 += red[8 + w]; }
            float mu = S1 * (1.f / 256.f);
            float var = S2 * (1.f / 256.f) - mu * mu;
            red[16] = mu;
            red[17] = rsqrtf(var + 1e-5f);
        }
        __syncthreads();
        float mu = red[16], rstd = red[17];
        out[(size_t)n * 256 + t] = (o - mu) * rstd * gamma[t] + beta[t];
        __syncthreads();
    }
}

// ---------------- launch ----------------
extern "C" void kernel_launch(void* const* d_in, const int* in_sizes, int n_in,
                              void* d_out, int out_size) {
    const float* x         = (const float*)d_in[0];
    const int*   src       = (const int*)d_in[1];
    const int*   trg       = (const int*)d_in[2];
    const int*   rel       = (const int*)d_in[3];
    // d_in[4] = node_to_graph_map (unused)
    const float* W_proj    = (const float*)d_in[5];
    const float* score_src = (const float*)d_in[6];
    const float* score_trg = (const float*)d_in[7];
    const float* W1        = (const float*)d_in[8];
    const float* b1        = (const float*)d_in[9];
    const float* W2        = (const float*)d_in[10];
    const float* b2        = (const float*)d_in[11];
    const float* W3        = (const float*)d_in[12];
    const float* b3        = (const float*)d_in[13];
    const float* W_skip    = (const float*)d_in[14];
    const float* bias      = (const float*)d_in[15];
    const float* gamma     = (const float*)d_in[16];
    const float* beta      = (const float*)d_in[17];
    float* out = (float*)d_out;

    cudaFuncSetAttribute(node2_kernel, cudaFuncAttributeMaxDynamicSharedMemorySize, NODE2_SMEM);
    cudaFuncSetAttribute(gemm_bf16_kernel, cudaFuncAttributeMaxDynamicSharedMemorySize, GSMEM);

    prep_wext_kernel<<<(CTOT * FIN + 511) / 512, 512>>>(W_proj, W_skip);
    prep_aext_kernel<<<8192, 256>>>(x);
    prep_w12_kernel<<<(2 * 64 * 64 + 255) / 256, 256>>>(W1, W2);
    zero_kernel<<<784, 256>>>();

    dim3 ggrid(CTOT / 128, (NN + 127) / 128);
    gemm_bf16_kernel<<<ggrid, 256, GSMEM>>>(score_src, score_trg);

    int eb = (NE + 255) / 256;
    edge1_kernel<<<eb, 256>>>(src, trg, rel);

    // counting sort by (trg, rel)
    hist_kernel<<<eb, 256>>>(trg, rel);
    scan1_kernel<<<NB1, 1024>>>();
    scan2_kernel<<<1, 256>>>();
    scan3_kernel<<<NB1, 1024>>>();
    scatter_kernel<<<eb, 256>>>(src, trg, rel);

    // atomic-free aggregation
    edge_agg_kernel<<<(NSEG * 32 + 255) / 256, 256>>>();

    node2_kernel<<<NN / 8, 256, NODE2_SMEM>>>(b1, b2, W3, b3, bias, gamma, beta, out);
}

// round 16
// speedup vs baseline: 1.5096x; 1.0476x over previous
#include <cuda_runtime.h>
#include <cuda_bf16.h>
#include <math.h>

// Problem constants
#define NN     50000
#define FIN    256
#define NH     4
#define NR     4
#define FF     64
#define NE     500000
#define CPROJ  1024          // NH*NR*FF
#define CTOT   1280          // CPROJ + NH*FF (skip)
#define NSEG   (NN * NR)     // 200000 segments, numbered r*NN + trg (r-major for L2 locality)
#define NB1    ((NSEG + 1023) / 1024)   // 196 scan blocks

// ---------------- scratch (device globals; no allocation allowed) ----------------
// proj layout PERMUTED: col = r*256 + h*64 + f   (skip still at cols 1024..1279, h*64+f)
__device__ float         g_ps[(size_t)NN * CTOT];
__device__ unsigned      g_aggp[(size_t)NSEG * NH * FF];   // packed bf16; index ((trg*4+r)*4+h)*64+f
__device__ float         g_ssrc[(size_t)NN * NH * NR];     // [n*16 + r*4 + h]
__device__ float         g_strg[(size_t)NN * NH * NR];
__device__ unsigned      g_m_u[NR * NH];                   // index q = r*4 + h
__device__ __align__(16) __nv_bfloat16 g_aext[(size_t)NN * 512];   // [n][512] = [x_hi | x_lo]
__device__ __align__(16) __nv_bfloat16 g_bext[(size_t)CTOT * 512]; // [c'][512] = [W_hi | W_lo]
__device__ __align__(16) __nv_bfloat16 g_w12[2 * 64 * 128];        // pre-split W1/W2 [hi(64)|lo(64)]
// edge sort scratch (seg = r*NN + trg)
__device__ int           g_cnt[NSEG];
__device__ int           g_off[NSEG + 1];
__device__ int           g_cur[NSEG];
__device__ int           g_bsum[256];
__device__ int           g_psrc[NE];                       // src[], permuted by segment

// ---------------- helpers ----------------
__device__ __forceinline__ unsigned fenc(float f) {
    unsigned u = __float_as_uint(f);
    return (u & 0x80000000u) ? ~u : (u | 0x80000000u);
}
__device__ __forceinline__ float fdec(unsigned u) {
    return (u & 0x80000000u) ? __uint_as_float(u & 0x7fffffffu) : __uint_as_float(~u);
}
__device__ __forceinline__ void bsplit(float w, __nv_bfloat16& hi, __nv_bfloat16& lo) {
    hi = __float2bfloat16(w);
    lo = __float2bfloat16(w - __bfloat162float(hi));
}
__device__ __forceinline__ unsigned bpack(__nv_bfloat16 h, __nv_bfloat16 l) {
    return ((unsigned)__bfloat16_as_ushort(l) << 16) | (unsigned)__bfloat16_as_ushort(h);
}
__device__ __forceinline__ void mma_bf16(float* c, unsigned a0, unsigned a1, unsigned a2,
                                         unsigned a3, unsigned b0, unsigned b1) {
    asm volatile(
        "mma.sync.aligned.m16n8k16.row.col.f32.bf16.bf16.f32 "
        "{%0,%1,%2,%3}, {%4,%5,%6,%7}, {%8,%9}, {%0,%1,%2,%3};\n"
        : "+f"(c[0]), "+f"(c[1]), "+f"(c[2]), "+f"(c[3])
        : "r"(a0), "r"(a1), "r"(a2), "r"(a3), "r"(b0), "r"(b1));
}
__device__ __forceinline__ void ldsm4(unsigned& r0, unsigned& r1, unsigned& r2, unsigned& r3,
                                      const void* p) {
    unsigned addr = (unsigned)__cvta_generic_to_shared(p);
    asm volatile("ldmatrix.sync.aligned.m8n8.x4.shared.b16 {%0,%1,%2,%3}, [%4];\n"
                 : "=r"(r0), "=r"(r1), "=r"(r2), "=r"(r3) : "r"(addr));
}
__device__ __forceinline__ void cp16(void* smem, const void* g, bool pred) {
    unsigned s = (unsigned)__cvta_generic_to_shared(smem);
    int sz = pred ? 16 : 0;
    asm volatile("cp.async.cg.shared.global [%0], [%1], 16, %2;\n" :: "r"(s), "l"(g), "r"(sz));
}
template <int N> __device__ __forceinline__ void cpwait() {
    asm volatile("cp.async.wait_group %0;\n" :: "n"(N) : "memory");
}

// ---------------- prep kernels ----------------
__global__ void prep_wext_kernel(const float* __restrict__ Wp, const float* __restrict__ Ws) {
    int idx = blockIdx.x * blockDim.x + threadIdx.x;
    if (idx >= CTOT * FIN) return;
    int c = idx >> 8, k = idx & 255;
    float w; int c2;
    if (c < CPROJ) {
        w = Wp[idx];
        int h = c >> 8, r = (c >> 6) & 3, f = c & 63;
        c2 = r * 256 + h * 64 + f;          // permuted: [r][h][f]
    } else {
        w = Ws[(c - CPROJ) * FIN + k];
        c2 = c;
    }
    __nv_bfloat16 hi, lo; bsplit(w, hi, lo);
    size_t b = (size_t)c2 * 512;
    g_bext[b + k] = hi; g_bext[b + 256 + k] = lo;
}

__global__ void prep_aext_kernel(const float* __restrict__ x) {
    int idx = blockIdx.x * blockDim.x + threadIdx.x;
    int tot = NN * FIN;
    for (; idx < tot; idx += gridDim.x * blockDim.x) {
        int n = idx >> 8, k = idx & 255;
        float w = x[idx];
        __nv_bfloat16 hi, lo; bsplit(w, hi, lo);
        size_t b = (size_t)n * 512;
        g_aext[b + k] = hi; g_aext[b + 256 + k] = lo;
    }
}

// pre-split node MLP weights into [hi(64) | lo(64)] rows of 128
__global__ void prep_w12_kernel(const float* __restrict__ W1, const float* __restrict__ W2) {
    int idx = blockIdx.x * blockDim.x + threadIdx.x;
    if (idx >= 2 * 64 * 64) return;
    int which = idx >> 12, rem = idx & 4095;
    int n_ = rem >> 6, k_ = rem & 63;
    float w = which ? W2[rem] : W1[rem];
    __nv_bfloat16 hi, lo; bsplit(w, hi, lo);
    int base = which * 64 * 128 + n_ * 128;
    g_w12[base + k_] = hi; g_w12[base + 64 + k_] = lo;
}

// ---------------- zero small scratch ----------------
__global__ void zero_kernel() {
    int idx = blockIdx.x * blockDim.x + threadIdx.x;
    for (int i = idx; i < NSEG; i += gridDim.x * blockDim.x) g_cnt[i] = 0;
    if (idx < NR * NH) g_m_u[idx] = 0u;
}

// ---------------- K2: bf16 TC GEMM — cp.async 2-stage, ldmatrix, fused scores ----------
#define GSTR  40                        // smem row stride in halves (80B)
#define TILEH (128 * GSTR)              // halves per 128x32 tile
#define TILEB (TILEH * 2)               // 10240 bytes
#define GSMEM (8 * TILEB + 512 * 4)     // 2 stages x 4 tiles + sred = 83968

__global__ void __launch_bounds__(256) gemm_bf16_kernel(const float* __restrict__ sv_src,
                                                        const float* __restrict__ sv_trg) {
    extern __shared__ char gsm[];
    __nv_bfloat16* A0h = reinterpret_cast<__nv_bfloat16*>(gsm);
    __nv_bfloat16* A0l = A0h + TILEH;
    __nv_bfloat16* B0h = A0l + TILEH;
    __nv_bfloat16* B0l = B0h + TILEH;
    __nv_bfloat16* A1h = B0l + TILEH;
    __nv_bfloat16* A1l = A1h + TILEH;
    __nv_bfloat16* B1h = A1l + TILEH;
    __nv_bfloat16* B1l = B1h + TILEH;
    float* sred = reinterpret_cast<float*>(gsm + 8 * TILEB);

    int t = threadIdx.x;
    int lane = t & 31, w = t >> 5;
    int wm = w >> 2, wn = w & 3;           // wm 0..1 (64 rows), wn 0..3 (32 cols)
    int g = lane >> 2, tg = lane & 3;
    int row0 = blockIdx.y * 128;
    int col0 = blockIdx.x * 128;

    float acc[4][4][4];
#pragma unroll
    for (int i = 0; i < 4; i++)
#pragma unroll
        for (int j = 0; j < 4; j++)
#pragma unroll
            for (int q = 0; q < 4; q++) acc[i][j][q] = 0.f;

    int r0v = t >> 2;                 // 0..63
    int kcv = (t & 3) * 8;            // 0,8,16,24
    int fr = lane & 15;
    int fcb = (lane >> 4) * 8;

    int ga0 = row0 + r0v, ga1 = row0 + r0v + 64;
    bool p0 = ga0 < NN, p1 = ga1 < NN;
    const __nv_bfloat16* apA0 = g_aext + (size_t)(p0 ? ga0 : 0) * 512 + kcv;
    const __nv_bfloat16* apA1 = g_aext + (size_t)(p1 ? ga1 : 0) * 512 + kcv;
    const __nv_bfloat16* bpB0 = g_bext + (size_t)(col0 + r0v) * 512 + kcv;
    const __nv_bfloat16* bpB1 = g_bext + (size_t)(col0 + r0v + 64) * 512 + kcv;
    int d0 = r0v * GSTR + kcv;
    int d1 = (r0v + 64) * GSTR + kcv;

    auto issue = [&](int c, __nv_bfloat16* Ah, __nv_bfloat16* Al,
                     __nv_bfloat16* Bh, __nv_bfloat16* Bl) {
        int k0 = c * 32;
        cp16(Ah + d0, apA0 + k0,       p0);
        cp16(Al + d0, apA0 + 256 + k0, p0);
        cp16(Ah + d1, apA1 + k0,       p1);
        cp16(Al + d1, apA1 + 256 + k0, p1);
        cp16(Bh + d0, bpB0 + k0,       true);
        cp16(Bl + d0, bpB0 + 256 + k0, true);
        cp16(Bh + d1, bpB1 + k0,       true);
        cp16(Bl + d1, bpB1 + 256 + k0, true);
        asm volatile("cp.async.commit_group;\n" ::: "memory");
    };

    auto compute = [&](const __nv_bfloat16* Ah, const __nv_bfloat16* Al,
                       const __nv_bfloat16* Bh, const __nv_bfloat16* Bl) {
#pragma unroll
        for (int kk = 0; kk < 32; kk += 16) {
            int fc = kk + fcb;
            unsigned bhf[2][4], blf[2][4];
#pragma unroll
            for (int np = 0; np < 2; np++) {
                int n = wn * 32 + np * 16 + fr;
                ldsm4(bhf[np][0], bhf[np][1], bhf[np][2], bhf[np][3], Bh + n * GSTR + fc);
                ldsm4(blf[np][0], blf[np][1], blf[np][2], blf[np][3], Bl + n * GSTR + fc);
            }
#pragma unroll
            for (int mt = 0; mt < 4; mt++) {
                int r = wm * 64 + mt * 16 + fr;
                unsigned a0, a1, a2, a3;
                ldsm4(a0, a1, a2, a3, Ah + r * GSTR + fc);
#pragma unroll
                for (int nt = 0; nt < 4; nt++) {
                    int np = nt >> 1, sel = nt & 1;
                    mma_bf16(acc[mt][nt], a0, a1, a2, a3, bhf[np][sel], bhf[np][sel + 2]);
                    mma_bf16(acc[mt][nt], a0, a1, a2, a3, blf[np][sel], blf[np][sel + 2]);
                }
            }
#pragma unroll
            for (int mt = 0; mt < 4; mt++) {
                int r = wm * 64 + mt * 16 + fr;
                unsigned a0, a1, a2, a3;
                ldsm4(a0, a1, a2, a3, Al + r * GSTR + fc);
#pragma unroll
                for (int nt = 0; nt < 4; nt++) {
                    int np = nt >> 1, sel = nt & 1;
                    mma_bf16(acc[mt][nt], a0, a1, a2, a3, bhf[np][sel], bhf[np][sel + 2]);
                }
            }
        }
    };

    issue(0, A0h, A0l, B0h, B0l);
    issue(1, A1h, A1l, B1h, B1l);

#pragma unroll
    for (int c = 0; c < 8; c++) {
        if (c < 7) cpwait<1>(); else cpwait<0>();
        __syncthreads();
        if ((c & 1) == 0) {
            compute(A0h, A0l, B0h, B0l);
            __syncthreads();
            if (c + 2 < 8) issue(c + 2, A0h, A0l, B0h, B0l);
        } else {
            compute(A1h, A1l, B1h, B1l);
            __syncthreads();
            if (c + 2 < 8) issue(c + 2, A1h, A1l, B1h, B1l);
        }
    }

    // write proj/skip
#pragma unroll
    for (int mt = 0; mt < 4; mt++)
#pragma unroll
        for (int nt = 0; nt < 4; nt++) {
            int row = row0 + wm * 64 + mt * 16 + g;
            int col = col0 + wn * 32 + nt * 8 + tg * 2;
            if (row < NN) {
                float2 o = make_float2(acc[mt][nt][0], acc[mt][nt][1]);
                *reinterpret_cast<float2*>(g_ps + (size_t)row * CTOT + col) = o;
            }
            if (row + 8 < NN) {
                float2 o = make_float2(acc[mt][nt][2], acc[mt][nt][3]);
                *reinterpret_cast<float2*>(g_ps + (size_t)(row + 8) * CTOT + col) = o;
            }
        }

    // fused attention-score epilogue (proj columns only; permuted slice q = r*4+h)
    if (col0 < CPROJ) {
        __syncthreads();
        for (int i = t; i < 512; i += 256) sred[i] = 0.f;
        __syncthreads();

        float sv[4][2], tv[4][2];
#pragma unroll
        for (int nt = 0; nt < 4; nt++)
#pragma unroll
            for (int qc = 0; qc < 2; qc++) {
                int c2 = col0 + wn * 32 + nt * 8 + tg * 2 + qc;
                int q = c2 >> 6;
                int rr_ = q >> 2, hh_ = q & 3;
                int corig = (hh_ * 4 + rr_) * 64 + (c2 & 63);
                sv[nt][qc] = sv_src[corig];
                tv[nt][qc] = sv_trg[corig];
            }
        int p_idx = wn >> 1;
#pragma unroll
        for (int mt = 0; mt < 4; mt++) {
            float s0 = 0.f, s1 = 0.f, t0 = 0.f, t1 = 0.f;
#pragma unroll
            for (int nt = 0; nt < 4; nt++)
#pragma unroll
                for (int qc = 0; qc < 2; qc++) {
                    s0 = fmaf(acc[mt][nt][qc],     sv[nt][qc], s0);
                    t0 = fmaf(acc[mt][nt][qc],     tv[nt][qc], t0);
                    s1 = fmaf(acc[mt][nt][2 + qc], sv[nt][qc], s1);
                    t1 = fmaf(acc[mt][nt][2 + qc], tv[nt][qc], t1);
                }
#pragma unroll
            for (int off = 1; off < 4; off <<= 1) {
                s0 += __shfl_xor_sync(0xffffffffu, s0, off);
                t0 += __shfl_xor_sync(0xffffffffu, t0, off);
                s1 += __shfl_xor_sync(0xffffffffu, s1, off);
                t1 += __shfl_xor_sync(0xffffffffu, t1, off);
            }
            if (tg == 0) {
                int r0 = wm * 64 + mt * 16 + g;
                atomicAdd(&sred[r0 * 4 + p_idx],           s0);
                atomicAdd(&sred[r0 * 4 + 2 + p_idx],       t0);
                atomicAdd(&sred[(r0 + 8) * 4 + p_idx],     s1);
                atomicAdd(&sred[(r0 + 8) * 4 + 2 + p_idx], t1);
            }
        }
        __syncthreads();
        int p0s = col0 >> 6;
        for (int i = t; i < 512; i += 256) {
            int row = i >> 2, j = i & 3;
            int n = row0 + row;
            if (n < NN) {
                float vval = sred[i];
                int p = p0s + (j & 1);
                if (j < 2) g_ssrc[n * 16 + p] = vval;
                else       g_strg[n * 16 + p] = vval;
            }
        }
    }
}

// ---------------- edge pass 1: per-(rel,head) max + fused histogram ----------------
__global__ void __launch_bounds__(256) edge1_kernel(const int* __restrict__ src,
                                                    const int* __restrict__ trg,
                                                    const int* __restrict__ rel) {
    __shared__ unsigned sm[16];
    int t = threadIdx.x;
    if (t < 16) sm[t] = 0u;
    __syncthreads();
    int e = blockIdx.x * 256 + t;
    if (e < NE) {
        int r = rel[e];
        int tgt = trg[e];
        atomicAdd(&g_cnt[r * NN + tgt], 1);   // fused histogram (seg = r*NN + trg)
        float4 a = *reinterpret_cast<const float4*>(g_ssrc + (size_t)src[e] * 16 + r * 4);
        float4 b = *reinterpret_cast<const float4*>(g_strg + (size_t)tgt * 16 + r * 4);
        float vv[4] = {a.x + b.x, a.y + b.y, a.z + b.z, a.w + b.w};
#pragma unroll
        for (int h = 0; h < 4; h++) {
            float v = (vv[h] > 0.f) ? vv[h] : 0.2f * vv[h];
            atomicMax(&sm[r * 4 + h], fenc(v));
        }
    }
    __syncthreads();
    if (t < 16 && sm[t] != 0u) atomicMax(&g_m_u[t], sm[t]);
}

// ---------------- counting sort: scan x3 / scatter (seg = r*NN + trg) ----------------
__global__ void __launch_bounds__(1024) scan1_kernel() {
    __shared__ int sd[1024];
    int t = threadIdx.x;
    int i = blockIdx.x * 1024 + t;
    int v = (i < NSEG) ? g_cnt[i] : 0;
    sd[t] = v;
    __syncthreads();
#pragma unroll
    for (int off = 1; off < 1024; off <<= 1) {
        int u = (t >= off) ? sd[t - off] : 0;
        __syncthreads();
        sd[t] += u;
        __syncthreads();
    }
    if (i < NSEG) g_off[i] = sd[t] - v;
    if (t == 1023) g_bsum[blockIdx.x] = sd[t];
}

__global__ void __launch_bounds__(256) scan2_kernel() {
    __shared__ int sd[256];
    int t = threadIdx.x;
    int v = (t < NB1) ? g_bsum[t] : 0;
    sd[t] = v;
    __syncthreads();
#pragma unroll
    for (int off = 1; off < 256; off <<= 1) {
        int u = (t >= off) ? sd[t - off] : 0;
        __syncthreads();
        sd[t] += u;
        __syncthreads();
    }
    if (t < NB1) g_bsum[t] = sd[t] - v;
    if (t == 0) g_off[NSEG] = NE;
}

__global__ void __launch_bounds__(1024) scan3_kernel() {
    int i = blockIdx.x * 1024 + threadIdx.x;
    if (i < NSEG) {
        int o = g_off[i] + g_bsum[blockIdx.x];
        g_off[i] = o;
        g_cur[i] = o;
    }
}

__global__ void scatter_kernel(const int* __restrict__ src, const int* __restrict__ trg,
                               const int* __restrict__ rel) {
    int e = blockIdx.x * 256 + threadIdx.x;
    if (e >= NE) return;
    int seg = rel[e] * NN + trg[e];
    int pos = atomicAdd(&g_cur[seg], 1);
    g_psrc[pos] = src[e];
}

// ---------------- segment aggregation: r-major order (L2-resident slice), 2-edge unroll ---
__global__ void __launch_bounds__(256) edge_agg_kernel() {
    int gw = (blockIdx.x * blockDim.x + threadIdx.x) >> 5;
    int lane = threadIdx.x & 31;
    if (gw >= NSEG) return;
    int seg = gw;
    int r = seg / NN;           // r-major: consecutive warps share one relation slice
    int tg = seg - r * NN;
    int beg = g_off[seg], end = g_off[seg + 1];

    float4 st4 = *reinterpret_cast<const float4*>(g_strg + (size_t)tg * 16 + r * 4);
    float strg_h[4] = {st4.x, st4.y, st4.z, st4.w};
    float m_h[4];
#pragma unroll
    for (int h = 0; h < 4; h++) m_h[h] = fdec(g_m_u[r * 4 + h]);

    float num0[4] = {0.f, 0.f, 0.f, 0.f};
    float num1[4] = {0.f, 0.f, 0.f, 0.f};
    float den[4]  = {0.f, 0.f, 0.f, 0.f};

    for (int i = beg; i < end; i += 2) {
        int sA = g_psrc[i];
        bool hb = (i + 1 < end);
        int sB = g_psrc[hb ? i + 1 : i];
        const float* pa = g_ps + (size_t)sA * CTOT + r * 256;
        const float* pb = g_ps + (size_t)sB * CTOT + r * 256;
        float4 spa = *reinterpret_cast<const float4*>(g_ssrc + (size_t)sA * 16 + r * 4);
        float4 spb = *reinterpret_cast<const float4*>(g_ssrc + (size_t)sB * 16 + r * 4);
        float svA[4] = {spa.x, spa.y, spa.z, spa.w};
        float svB[4] = {spb.x, spb.y, spb.z, spb.w};
        float gA0[4], gA1[4], gB0[4], gB1[4];
#pragma unroll
        for (int h = 0; h < 4; h++) {
            gA0[h] = pa[h * 64 + lane];
            gA1[h] = pa[h * 64 + lane + 32];
            gB0[h] = pb[h * 64 + lane];
            gB1[h] = pb[h * 64 + lane + 32];
        }
        float bm = hb ? 1.f : 0.f;
#pragma unroll
        for (int h = 0; h < 4; h++) {
            float vA = svA[h] + strg_h[h];
            vA = (vA > 0.f) ? vA : 0.2f * vA;
            float exA = expf(vA - m_h[h]);
            float vB = svB[h] + strg_h[h];
            vB = (vB > 0.f) ? vB : 0.2f * vB;
            float exB = expf(vB - m_h[h]) * bm;
            den[h] += exA + exB;
            num0[h] = fmaf(exA, gA0[h], num0[h]);
            num1[h] = fmaf(exA, gA1[h], num1[h]);
            num0[h] = fmaf(exB, gB0[h], num0[h]);
            num1[h] = fmaf(exB, gB1[h], num1[h]);
        }
    }
#pragma unroll
    for (int h = 0; h < 4; h++) {
        float inv = 1.f / (den[h] + 1e-16f);
        // keep node2's layout: index by (trg*4 + r)
        unsigned* ag = g_aggp + (((size_t)tg * 4 + r) * 4 + h) * 64;
        __nv_bfloat16 hi, lo;
        bsplit(num0[h] * inv, hi, lo); ag[lane]      = bpack(hi, lo);
        bsplit(num1[h] * inv, hi, lo); ag[lane + 32] = bpack(hi, lo);
    }
}

// ---------------- fused node kernel with tensor-core MLP (compact [hi|lo] layout) --------
#define NS2 136   // smem row stride in halves (272B) — conflict-free ldmatrix
#define NODE2_SMEM ((128 + 128 + 64 + 64) * NS2 * 2 + (64*3 + 128*2 + 32) * 4)

// 3-pass split mma over [hi(64)|lo(64)] tiles: A_hi*W_hi + A_lo*W_hi + A_hi*W_lo
__device__ __forceinline__ void mlp_layer(const __nv_bfloat16* __restrict__ Ain,
                                          const __nv_bfloat16* __restrict__ Wm,
                                          const float* __restrict__ bs,
                                          __nv_bfloat16* __restrict__ Hout, int t) {
    int lane = t & 31, w = t >> 5;
    int wm = w >> 2, wn = w & 3;
    int g = lane >> 2, tg = lane & 3;
    float acc[4][2][4];
#pragma unroll
    for (int i = 0; i < 4; i++)
#pragma unroll
        for (int j = 0; j < 2; j++)
#pragma unroll
            for (int q = 0; q < 4; q++) acc[i][j][q] = 0.f;

#pragma unroll
    for (int pass = 0; pass < 3; pass++) {
        int aoff = (pass == 1) ? 64 : 0;
        int woff = (pass == 2) ? 64 : 0;
#pragma unroll
        for (int ks = 0; ks < 4; ks++) {
            int kk = ks * 16;
            unsigned af[4][4], bf_[2][2];
#pragma unroll
            for (int mt = 0; mt < 4; mt++) {
                const __nv_bfloat16* ap = Ain + (wm * 64 + mt * 16 + g) * NS2 + aoff + kk + tg * 2;
                af[mt][0] = *reinterpret_cast<const unsigned*>(ap);
                af[mt][1] = *reinterpret_cast<const unsigned*>(ap + 8 * NS2);
                af[mt][2] = *reinterpret_cast<const unsigned*>(ap + 8);
                af[mt][3] = *reinterpret_cast<const unsigned*>(ap + 8 * NS2 + 8);
            }
#pragma unroll
            for (int nt = 0; nt < 2; nt++) {
                const __nv_bfloat16* bp = Wm + (wn * 16 + nt * 8 + g) * NS2 + woff + kk + tg * 2;
                bf_[nt][0] = *reinterpret_cast<const unsigned*>(bp);
                bf_[nt][1] = *reinterpret_cast<const unsigned*>(bp + 8);
            }
#pragma unroll
            for (int mt = 0; mt < 4; mt++)
#pragma unroll
                for (int nt = 0; nt < 2; nt++)
                    mma_bf16(acc[mt][nt], af[mt][0], af[mt][1], af[mt][2], af[mt][3],
                             bf_[nt][0], bf_[nt][1]);
        }
    }
    __syncthreads();
#pragma unroll
    for (int mt = 0; mt < 4; mt++)
#pragma unroll
        for (int nt = 0; nt < 2; nt++) {
            int row = wm * 64 + mt * 16 + g;
            int col = wn * 16 + nt * 8 + tg * 2;
#pragma unroll
            for (int q = 0; q < 4; q++) {
                int rr = row + ((q >> 1) ? 8 : 0);
                int cc = col + (q & 1);
                float h = fmaxf(acc[mt][nt][q] + bs[cc], 0.f);
                __nv_bfloat16 hi, lo; bsplit(h, hi, lo);
                Hout[rr * NS2 + cc] = hi;
                Hout[rr * NS2 + 64 + cc] = lo;
            }
        }
    __syncthreads();
}

__global__ void __launch_bounds__(256) node2_kernel(
        const float* __restrict__ b1, const float* __restrict__ b2,
        const float* __restrict__ W3, const float* __restrict__ b3,
        const float* __restrict__ bias, const float* __restrict__ gamma,
        const float* __restrict__ beta, float* __restrict__ out) {
    extern __shared__ char nsm[];
    __nv_bfloat16* Asp = reinterpret_cast<__nv_bfloat16*>(nsm);
    __nv_bfloat16* Hsp = Asp + 128 * NS2;
    __nv_bfloat16* W1s = Hsp + 128 * NS2;
    __nv_bfloat16* W2s = W1s + 64 * NS2;
    float* W3s  = reinterpret_cast<float*>(W2s + 64 * NS2);
    float* b1s  = W3s + 64;
    float* b2s  = b1s + 64;
    float* scs  = b2s + 64;
    float* alps = scs + 128;
    float* red  = alps + 128;

    int t = threadIdx.x;
    int node0 = blockIdx.x * 8;

    // load pre-split weights via uint4 (row stride NS2=136 halves = 272B, 16B-aligned)
    for (int idx = t; idx < 2048; idx += 256) {
        int which = idx >= 1024;
        int rem = which ? idx - 1024 : idx;
        int n_ = rem >> 4, c8 = rem & 15;
        uint4 v = reinterpret_cast<const uint4*>(g_w12)[idx];
        __nv_bfloat16* dst = (which ? W2s : W1s) + n_ * NS2 + c8 * 8;
        *reinterpret_cast<uint4*>(dst) = v;
    }
    if (t < 64) { W3s[t] = W3[t]; b1s[t] = b1[t]; b2s[t] = b2[t]; }

    // load packed agg; Asp row = ln*16 + h*4 + r, layout [hi | lo]
    for (int idx = t; idx < 8192; idx += 256) {
        int row = idx >> 6, f = idx & 63;
        int ln = row >> 4, p = row & 15, h = p >> 2, r = p & 3;
        int n = node0 + ln;
        unsigned u = g_aggp[(((size_t)n * 4 + r) * 4 + h) * 64 + f];
        __nv_bfloat16 hi = __ushort_as_bfloat16((unsigned short)(u & 0xffffu));
        __nv_bfloat16 lo = __ushort_as_bfloat16((unsigned short)(u >> 16));
        Asp[row * NS2 + f] = hi; Asp[row * NS2 + 64 + f] = lo;
    }
    __syncthreads();

    mlp_layer(Asp, W1s, b1s, Hsp, t);
    mlp_layer(Hsp, W2s, b2s, Hsp, t);

    if (t < 128) {
        float sacc = b3[0];
        const __nv_bfloat16* hp = Hsp + t * NS2;
#pragma unroll
        for (int j = 0; j < 64; j++) {
            float hv = __bfloat162float(hp[j]) + __bfloat162float(hp[64 + j]);
            sacc = fmaf(hv, W3s[j], sacc);
        }
        float sp = (sacc > 20.f) ? sacc : log1pf(expf(sacc));
        scs[t] = sacc * tanhf(sp);
    }
    __syncthreads();

    if (t < 32) {
        int base = (t >> 2) * 16 + (t & 3) * 4;
        float mx = -1e30f;
#pragma unroll
        for (int r = 0; r < 4; r++) mx = fmaxf(mx, scs[base + r]);
        float ev[4], ssum = 0.f;
#pragma unroll
        for (int r = 0; r < 4; r++) { ev[r] = expf(scs[base + r] - mx); ssum += ev[r]; }
#pragma unroll
        for (int r = 0; r < 4; r++) alps[base + r] = ev[r] / ssum;
    }
    __syncthreads();

    int hh = t >> 6, f = t & 63;
    int wid = t >> 5, lane = t & 31;
#pragma unroll 1
    for (int s = 0; s < 8; s++) {
        int n = node0 + s;
        int rb = s * 16 + hh * 4;
        float o = 0.f;
#pragma unroll
        for (int r = 0; r < 4; r++) {
            const __nv_bfloat16* ap = Asp + (rb + r) * NS2;
            float a = __bfloat162float(ap[f]) + __bfloat162float(ap[64 + f]);
            o = fmaf(a, alps[rb + r], o);
        }
        o += g_ps[(size_t)n * CTOT + CPROJ + t];
        o += bias[t];
        o = (o > 0.f) ? o : expm1f(o);

        float s1 = o, s2 = o * o;
#pragma unroll
        for (int off = 16; off > 0; off >>= 1) {
            s1 += __shfl_down_sync(0xffffffffu, s1, off);
            s2 += __shfl_down_sync(0xffffffffu, s2, off);
        }
        if (lane == 0) { red[wid] = s1; red[8 + wid] = s2; }
        __syncthreads();
        if (t == 0) {
            float S1 = 0.f, S2 = 0.f;
#pragma unroll
            for (int w = 0; w < 8; w++) { S1 += red[w]; S2 += red[8 + w]; }
            float mu = S1 * (1.f / 256.f);
            float var = S2 * (1.f / 256.f) - mu * mu;
            red[16] = mu;
            red[17] = rsqrtf(var + 1e-5f);
        }
        __syncthreads();
        float mu = red[16], rstd = red[17];
        out[(size_t)n * 256 + t] = (o - mu) * rstd * gamma[t] + beta[t];
        __syncthreads();
    }
}

// ---------------- launch ----------------
extern "C" void kernel_launch(void* const* d_in, const int* in_sizes, int n_in,
                              void* d_out, int out_size) {
    const float* x         = (const float*)d_in[0];
    const int*   src       = (const int*)d_in[1];
    const int*   trg       = (const int*)d_in[2];
    const int*   rel       = (const int*)d_in[3];
    // d_in[4] = node_to_graph_map (unused)
    const float* W_proj    = (const float*)d_in[5];
    const float* score_src = (const float*)d_in[6];
    const float* score_trg = (const float*)d_in[7];
    const float* W1        = (const float*)d_in[8];
    const float* b1        = (const float*)d_in[9];
    const float* W2        = (const float*)d_in[10];
    const float* b2        = (const float*)d_in[11];
    const float* W3        = (const float*)d_in[12];
    const float* b3        = (const float*)d_in[13];
    const float* W_skip    = (const float*)d_in[14];
    const float* bias      = (const float*)d_in[15];
    const float* gamma     = (const float*)d_in[16];
    const float* beta      = (const float*)d_in[17];
    float* out = (float*)d_out;

    cudaFuncSetAttribute(node2_kernel, cudaFuncAttributeMaxDynamicSharedMemorySize, NODE2_SMEM);
    cudaFuncSetAttribute(gemm_bf16_kernel, cudaFuncAttributeMaxDynamicSharedMemorySize, GSMEM);

    prep_wext_kernel<<<(CTOT * FIN + 511) / 512, 512>>>(W_proj, W_skip);
    prep_aext_kernel<<<8192, 256>>>(x);
    prep_w12_kernel<<<(2 * 64 * 64 + 255) / 256, 256>>>(W1, W2);
    zero_kernel<<<784, 256>>>();

    dim3 ggrid(CTOT / 128, (NN + 127) / 128);
    gemm_bf16_kernel<<<ggrid, 256, GSMEM>>>(score_src, score_trg);

    int eb = (NE + 255) / 256;
    edge1_kernel<<<eb, 256>>>(src, trg, rel);   // max + fused histogram

    scan1_kernel<<<NB1, 1024>>>();
    scan2_kernel<<<1, 256>>>();
    scan3_kernel<<<NB1, 1024>>>();
    scatter_kernel<<<eb, 256>>>(src, trg, rel);

    // atomic-free aggregation (r-major segments)
    edge_agg_kernel<<<(NSEG * 32 + 255) / 256, 256>>>();

    node2_kernel<<<NN / 8, 256, NODE2_SMEM>>>(b1, b2, W3, b3, bias, gamma, beta, out);
}